// round 6
// baseline (speedup 1.0000x reference)
#include <cuda_runtime.h>
#include <cuda_bf16.h>
#include <cstdint>

#define Bb    16
#define T     256
#define NJ    24
#define C     512
#define H     8
#define HD    64
#define BATCH (Bb*NJ)     // 384
#define RTOT  (BATCH*T)   // 98304

// ---------------- scratch (static device memory; no allocations) ----------------
__device__ float g_q[(size_t)RTOT * C];
__device__ float g_k[(size_t)RTOT * C];
__device__ float g_v[(size_t)RTOT * C];
__device__ float g_mu[2 * RTOT];
__device__ float g_rstd[2 * RTOT];

// ---------------- helpers ----------------
__device__ __forceinline__ uint32_t smem_u32(const void* p) {
    uint32_t a;
    asm("{ .reg .u64 t; cvta.to.shared.u64 t, %1; cvt.u32.u64 %0, t; }" : "=r"(a) : "l"(p));
    return a;
}

__device__ __forceinline__ void ldsm_x4(uint32_t* r, uint32_t addr) {
    asm volatile("ldmatrix.sync.aligned.m8n8.x4.shared.b16 {%0,%1,%2,%3}, [%4];"
                 : "=r"(r[0]), "=r"(r[1]), "=r"(r[2]), "=r"(r[3]) : "r"(addr));
}
__device__ __forceinline__ void mma16816(float* c, const uint32_t* a,
                                         uint32_t b0, uint32_t b1) {
    asm volatile("mma.sync.aligned.m16n8k16.row.col.f32.bf16.bf16.f32 "
                 "{%0,%1,%2,%3}, {%4,%5,%6,%7}, {%8,%9}, {%0,%1,%2,%3};"
                 : "+f"(c[0]), "+f"(c[1]), "+f"(c[2]), "+f"(c[3])
                 : "r"(a[0]), "r"(a[1]), "r"(a[2]), "r"(a[3]), "r"(b0), "r"(b1));
}

__device__ __forceinline__ uint32_t pack_hi_lo(float f0, float f1, uint32_t& lo) {
    __nv_bfloat16 a = __float2bfloat16(f0);
    __nv_bfloat16 b = __float2bfloat16(f1);
    __nv_bfloat162 hp(a, b);
    __nv_bfloat162 lp(__float2bfloat16(f0 - __bfloat162float(a)),
                      __float2bfloat16(f1 - __bfloat162float(b)));
    lo = *reinterpret_cast<uint32_t*>(&lp);
    return *reinterpret_cast<uint32_t*>(&hp);
}

// chunk swizzle for 64B rows: 4 chunks of 16B, XOR by (row>>1)&3 -> conflict-free
#define SW(r, c) (((c) ^ (((r) >> 1) & 3)))

// ---------------- kernel 1: per-row LN statistics ----------------
__global__ void ln_stats_kernel(const float* __restrict__ x,
                                const float* __restrict__ cx) {
    int warp = threadIdx.x >> 5, lane = threadIdx.x & 31;
    int row = blockIdx.x * 8 + warp;
    const float* src = (row < RTOT) ? x : cx;
    int r  = (row < RTOT) ? row : row - RTOT;
    int bidx = r >> 8;
    int t    = r & 255;
    int bb = bidx / NJ, n = bidx % NJ;
    const float4* p = (const float4*)(src + ((size_t)(bb * T + t) * NJ + n) * C);
    float s = 0.f, sq = 0.f;
#pragma unroll
    for (int i = 0; i < 4; i++) {
        float4 v = p[lane + 32 * i];
        s  += v.x + v.y + v.z + v.w;
        sq += v.x * v.x + v.y * v.y + v.z * v.z + v.w * v.w;
    }
#pragma unroll
    for (int o = 16; o; o >>= 1) {
        s  += __shfl_xor_sync(0xffffffffu, s, o);
        sq += __shfl_xor_sync(0xffffffffu, sq, o);
    }
    if (lane == 0) {
        float mu  = s * (1.0f / C);
        float var = sq * (1.0f / C) - mu * mu;
        g_mu[row]   = mu;
        g_rstd[row] = rsqrtf(var + 1e-5f);
    }
}

// ---------------- kernel 2: QKV GEMM via mma.sync bf16 split (fused LN) ----------------
// D[r,o] = sum_c LN(A[r,c]) * W[o,c].  BM=BN=128, BK=32.
// 8 warps: 4 (M) x 2 (N); warp tile 32x64. Split: D += Ah*Bh + Ah*Bl + Al*Bh.
__global__ __launch_bounds__(256, 1) void qkv_gemm_mma(
    const float* __restrict__ x, const float* __restrict__ cx,
    const float* __restrict__ gamma, const float* __restrict__ beta,
    const float* __restrict__ Wq, const float* __restrict__ Wk,
    const float* __restrict__ Wv) {
    __shared__ char sAh[128 * 64];   // 128 rows x 32 bf16 (64B), swizzled
    __shared__ char sAl[128 * 64];
    __shared__ char sBh[128 * 64];   // [n][k] rows
    __shared__ char sBl[128 * 64];
    __shared__ float sMu[128], sRs[128];

    int tid = threadIdx.x;
    int wid = tid >> 5, lane = tid & 31;
    int wm = wid & 3, wn = wid >> 2;          // 4 x 2 warp grid

    int z = blockIdx.z;
    const float* A = (z == 0) ? x : cx;
    const float* W = (z == 0) ? Wq : (z == 1) ? Wk : Wv;
    float* dst     = (z == 0) ? g_q : (z == 1) ? g_k : g_v;
    int muOff      = (z == 0) ? 0 : RTOT;

    int r0 = blockIdx.y * 128;
    int o0 = blockIdx.x * 128;
    int bidx = r0 >> 8;
    int t0   = r0 & 255;
    int bb = bidx / NJ, n = bidx % NJ;
    size_t baseA = ((size_t)(bb * T + t0) * NJ + n) * C;

    if (tid < 128) {
        sMu[tid] = g_mu[muOff + r0 + tid];
        sRs[tid] = g_rstd[muOff + r0 + tid];
    }
    __syncthreads();

    float acc[2][8][4];
#pragma unroll
    for (int i = 0; i < 2; i++)
#pragma unroll
        for (int j = 0; j < 8; j++)
#pragma unroll
            for (int q = 0; q < 4; q++) acc[i][j][q] = 0.f;

    // ldmatrix source rows (within the 128-row tile)
    int a_row = wm * 32 + (lane & 15);        // + mt*16
    int a_khalf = lane >> 4;
    int b_nrow = wn * 64 + (lane & 7) + ((lane >> 4) << 3);  // + ng*16
    int b_khalf = (lane >> 3) & 1;

    uint32_t uAh = smem_u32(sAh), uAl = smem_u32(sAl);
    uint32_t uBh = smem_u32(sBh), uBl = smem_u32(sBl);

    for (int k0 = 0; k0 < C; k0 += 32) {
        // ---- fill: 512 chunks (128 rows x 4 x 16B) per tile, 2 per thread ----
#pragma unroll
        for (int l = 0; l < 2; ++l) {
            int idx = tid + l * 256;          // 0..511
            int rr = idx >> 2;                // row 0..127
            int cc = idx & 3;                 // 16B chunk -> 8 k values
            int kk = k0 + cc * 8;
            // A with fused LN
            const float* ap = A + baseA + (size_t)rr * (NJ * C) + kk;
            float4 v0 = *(const float4*)ap;
            float4 v1 = *(const float4*)(ap + 4);
            float m = sMu[rr], rs = sRs[rr];
            float4 g0 = *(const float4*)(gamma + kk);
            float4 g1 = *(const float4*)(gamma + kk + 4);
            float4 e0 = *(const float4*)(beta + kk);
            float4 e1 = *(const float4*)(beta + kk + 4);
            float f0 = (v0.x - m) * rs * g0.x + e0.x;
            float f1 = (v0.y - m) * rs * g0.y + e0.y;
            float f2 = (v0.z - m) * rs * g0.z + e0.z;
            float f3 = (v0.w - m) * rs * g0.w + e0.w;
            float f4 = (v1.x - m) * rs * g1.x + e1.x;
            float f5 = (v1.y - m) * rs * g1.y + e1.y;
            float f6 = (v1.z - m) * rs * g1.z + e1.z;
            float f7 = (v1.w - m) * rs * g1.w + e1.w;
            uint4 hi, lo;
            hi.x = pack_hi_lo(f0, f1, lo.x);
            hi.y = pack_hi_lo(f2, f3, lo.y);
            hi.z = pack_hi_lo(f4, f5, lo.z);
            hi.w = pack_hi_lo(f6, f7, lo.w);
            uint32_t soff = (uint32_t)(rr * 64 + SW(rr, cc) * 16);
            *(uint4*)(sAh + soff) = hi;
            *(uint4*)(sAl + soff) = lo;
            // B: W row (o0+rr), k-contiguous
            const float* wp = W + (size_t)(o0 + rr) * C + kk;
            float4 w0 = *(const float4*)wp;
            float4 w1 = *(const float4*)(wp + 4);
            uint4 whi, wlo;
            whi.x = pack_hi_lo(w0.x, w0.y, wlo.x);
            whi.y = pack_hi_lo(w0.z, w0.w, wlo.y);
            whi.z = pack_hi_lo(w1.x, w1.y, wlo.z);
            whi.w = pack_hi_lo(w1.z, w1.w, wlo.w);
            *(uint4*)(sBh + soff) = whi;
            *(uint4*)(sBl + soff) = wlo;
        }
        __syncthreads();

        // ---- compute: 2 k16 steps ----
#pragma unroll
        for (int ks = 0; ks < 2; ++ks) {
            int a_chunk = ks * 2 + a_khalf;
            int b_chunk = ks * 2 + b_khalf;
            uint32_t ah[2][4], al[2][4];
#pragma unroll
            for (int mt = 0; mt < 2; ++mt) {
                int row = a_row + mt * 16;
                uint32_t off = (uint32_t)(row * 64 + SW(row, a_chunk) * 16);
                ldsm_x4(ah[mt], uAh + off);
                ldsm_x4(al[mt], uAl + off);
            }
            // B stored [n][k] (K-contiguous) -> NON-trans ldmatrix gives the
            // col-major B fragment (n = lane/4, k = (lane%4)*2) directly.
            uint32_t bh[4][4], bl[4][4];
#pragma unroll
            for (int ng = 0; ng < 4; ++ng) {
                int nr = b_nrow + ng * 16;
                uint32_t off = (uint32_t)(nr * 64 + SW(nr, b_chunk) * 16);
                ldsm_x4(bh[ng], uBh + off);
                ldsm_x4(bl[ng], uBl + off);
            }
#pragma unroll
            for (int mt = 0; mt < 2; ++mt)
#pragma unroll
                for (int ng = 0; ng < 4; ++ng) {
#pragma unroll
                    for (int hf = 0; hf < 2; ++hf) {
                        float* c = acc[mt][ng * 2 + hf];
                        mma16816(c, ah[mt], bh[ng][2 * hf], bh[ng][2 * hf + 1]);
                        mma16816(c, ah[mt], bl[ng][2 * hf], bl[ng][2 * hf + 1]);
                        mma16816(c, al[mt], bh[ng][2 * hf], bh[ng][2 * hf + 1]);
                    }
                }
        }
        __syncthreads();
    }

    // ---- epilogue ----
    int qr = lane >> 2, qc = (lane & 3) * 2;
#pragma unroll
    for (int mt = 0; mt < 2; ++mt) {
        int row = r0 + wm * 32 + mt * 16 + qr;
#pragma unroll
        for (int nt = 0; nt < 8; ++nt) {
            int col = o0 + wn * 64 + nt * 8 + qc;
            float* c = acc[mt][nt];
            *(float2*)(dst + (size_t)row * C + col)       = make_float2(c[0], c[1]);
            *(float2*)(dst + (size_t)(row + 8) * C + col) = make_float2(c[2], c[3]);
        }
    }
}

// ---------------- kernel 3: attention + residual + output transpose ----------------
__global__ __launch_bounds__(256, 1) void attn_kernel(const float* __restrict__ x,
                                                      float* __restrict__ out) {
    extern __shared__ float4 sm4[];
    float4* ks = sm4;
    float4* vs = sm4 + 256 * 16;

    int bi = blockIdx.x / H;
    int h  = blockIdx.x % H;
    size_t base = (size_t)bi * T * C + h * HD;
    const float4* kg = (const float4*)(g_k + base);
    const float4* vg = (const float4*)(g_v + base);
    int tid = threadIdx.x;

    for (int i = tid; i < 256 * 16; i += 256) {
        int r = i >> 4, c = i & 15;
        ks[i] = kg[(size_t)r * (C / 4) + c];
        vs[i] = vg[(size_t)r * (C / 4) + c];
    }
    __syncthreads();

    const float4* qg = (const float4*)(g_q + base + (size_t)tid * C);
    float4 q4[16];
#pragma unroll
    for (int i = 0; i < 16; i++) q4[i] = qg[i];

    float4 a4[16];
#pragma unroll
    for (int i = 0; i < 16; i++) a4[i] = make_float4(0.f, 0.f, 0.f, 0.f);
    float ssum = 0.f;

    for (int m = 0; m < 256; m++) {
        const float4* kr = ks + m * 16;
        float p0 = 0.f, p1 = 0.f, p2 = 0.f, p3 = 0.f;
#pragma unroll
        for (int i = 0; i < 16; i++) {
            float4 kv = kr[i];
            p0 += q4[i].x * kv.x;
            p1 += q4[i].y * kv.y;
            p2 += q4[i].z * kv.z;
            p3 += q4[i].w * kv.w;
        }
        float s = ((p0 + p1) + (p2 + p3)) * 0.125f;
        float e = __expf(s);
        ssum += e;
        const float4* vr = vs + m * 16;
#pragma unroll
        for (int i = 0; i < 16; i++) {
            float4 vv = vr[i];
            a4[i].x += e * vv.x;
            a4[i].y += e * vv.y;
            a4[i].z += e * vv.z;
            a4[i].w += e * vv.w;
        }
    }
    float inv = 1.0f / ssum;

    int bb = bi / NJ, n = bi % NJ;
    size_t oo = ((size_t)(bb * T + tid) * NJ + n) * C + h * HD;
    const float4* xg = (const float4*)(x + oo);
    float4* og = (float4*)(out + oo);
#pragma unroll
    for (int i = 0; i < 16; i++) {
        float4 xv = xg[i];
        og[i] = make_float4(xv.x + a4[i].x * inv, xv.y + a4[i].y * inv,
                            xv.z + a4[i].z * inv, xv.w + a4[i].w * inv);
    }
}

// ---------------- launch ----------------
extern "C" void kernel_launch(void* const* d_in, const int* in_sizes, int n_in,
                              void* d_out, int out_size) {
    const float* x     = (const float*)d_in[0];
    const float* cx    = (const float*)d_in[1];
    const float* gamma = (const float*)d_in[2];
    const float* beta  = (const float*)d_in[3];
    const float* Wq    = (const float*)d_in[4];
    const float* Wk    = (const float*)d_in[5];
    const float* Wv    = (const float*)d_in[6];
    float* out = (float*)d_out;

    cudaFuncSetAttribute(attn_kernel, cudaFuncAttributeMaxDynamicSharedMemorySize, 131072);

    ln_stats_kernel<<<2 * RTOT / 8, 256>>>(x, cx);

    dim3 gg(C / 128, RTOT / 128, 3);
    qkv_gemm_mma<<<gg, 256>>>(x, cx, gamma, beta, Wq, Wk, Wv);

    attn_kernel<<<BATCH * H, 256, 131072>>>(x, out);
}

// round 7
// speedup vs baseline: 1.9573x; 1.9573x over previous
#include <cuda_runtime.h>
#include <cuda_bf16.h>
#include <cstdint>

#define Bb    16
#define T     256
#define NJ    24
#define C     512
#define H     8
#define HD    64
#define BATCH (Bb*NJ)     // 384
#define RTOT  (BATCH*T)   // 98304

// ---------------- scratch (static device memory; no allocations) ----------------
__device__ float g_q[(size_t)RTOT * C];
__device__ float g_k[(size_t)RTOT * C];
__device__ float g_v[(size_t)RTOT * C];
// packed bf16 hi/lo operands (uint4 base => 16B alignment for cp.async)
__device__ uint4 g_xh4[(size_t)RTOT * C / 8];
__device__ uint4 g_xl4[(size_t)RTOT * C / 8];
__device__ uint4 g_ch4[(size_t)RTOT * C / 8];
__device__ uint4 g_cl4[(size_t)RTOT * C / 8];
__device__ uint4 g_wh4[(size_t)3 * C * C / 8];
__device__ uint4 g_wl4[(size_t)3 * C * C / 8];

// ---------------- helpers ----------------
__device__ __forceinline__ uint32_t smem_u32(const void* p) {
    uint32_t a;
    asm("{ .reg .u64 t; cvta.to.shared.u64 t, %1; cvt.u32.u64 %0, t; }" : "=r"(a) : "l"(p));
    return a;
}
__device__ __forceinline__ void cp16(uint32_t dst, const void* src) {
    asm volatile("cp.async.cg.shared.global [%0], [%1], 16;" :: "r"(dst), "l"(src));
}
#define CP_COMMIT() asm volatile("cp.async.commit_group;" ::: "memory")
#define CP_WAIT1()  asm volatile("cp.async.wait_group 1;" ::: "memory")
#define CP_WAIT0()  asm volatile("cp.async.wait_group 0;" ::: "memory")

__device__ __forceinline__ void ldsm_x4(uint32_t* r, uint32_t addr) {
    asm volatile("ldmatrix.sync.aligned.m8n8.x4.shared.b16 {%0,%1,%2,%3}, [%4];"
                 : "=r"(r[0]), "=r"(r[1]), "=r"(r[2]), "=r"(r[3]) : "r"(addr));
}
__device__ __forceinline__ void mma16816(float* c, const uint32_t* a,
                                         uint32_t b0, uint32_t b1) {
    asm volatile("mma.sync.aligned.m16n8k16.row.col.f32.bf16.bf16.f32 "
                 "{%0,%1,%2,%3}, {%4,%5,%6,%7}, {%8,%9}, {%0,%1,%2,%3};"
                 : "+f"(c[0]), "+f"(c[1]), "+f"(c[2]), "+f"(c[3])
                 : "r"(a[0]), "r"(a[1]), "r"(a[2]), "r"(a[3]), "r"(b0), "r"(b1));
}
__device__ __forceinline__ uint32_t pack_hi_lo(float f0, float f1, uint32_t& lo) {
    __nv_bfloat16 a = __float2bfloat16(f0);
    __nv_bfloat16 b = __float2bfloat16(f1);
    __nv_bfloat162 hp(a, b);
    __nv_bfloat162 lp(__float2bfloat16(f0 - __bfloat162float(a)),
                      __float2bfloat16(f1 - __bfloat162float(b)));
    lo = *reinterpret_cast<uint32_t*>(&lp);
    return *reinterpret_cast<uint32_t*>(&hp);
}

// ---------------- kernel 1: LN stats + apply + bf16 hi/lo pack (one pass) ----------------
__global__ void ln_pack_kernel(const float* __restrict__ x, const float* __restrict__ cx,
                               const float* __restrict__ gamma, const float* __restrict__ beta) {
    int warp = threadIdx.x >> 5, lane = threadIdx.x & 31;
    int row = blockIdx.x * 8 + warp;                 // 0..2*RTOT-1
    const float* src = (row < RTOT) ? x : cx;
    int r  = (row < RTOT) ? row : row - RTOT;        // folded row index
    int bidx = r >> 8;
    int t    = r & 255;
    int bb = bidx / NJ, n = bidx % NJ;
    const float4* p = (const float4*)(src + ((size_t)(bb * T + t) * NJ + n) * C);
    float4 v[4];
    float s = 0.f, sq = 0.f;
#pragma unroll
    for (int i = 0; i < 4; i++) {
        v[i] = p[lane + 32 * i];
        s  += v[i].x + v[i].y + v[i].z + v[i].w;
        sq += v[i].x * v[i].x + v[i].y * v[i].y + v[i].z * v[i].z + v[i].w * v[i].w;
    }
#pragma unroll
    for (int o = 16; o; o >>= 1) {
        s  += __shfl_xor_sync(0xffffffffu, s, o);
        sq += __shfl_xor_sync(0xffffffffu, sq, o);
    }
    float mu  = s * (1.0f / C);
    float rs  = rsqrtf(sq * (1.0f / C) - mu * mu + 1e-5f);

    __nv_bfloat16* dh = (row < RTOT) ? (__nv_bfloat16*)g_xh4 : (__nv_bfloat16*)g_ch4;
    __nv_bfloat16* dl = (row < RTOT) ? (__nv_bfloat16*)g_xl4 : (__nv_bfloat16*)g_cl4;
    size_t rb = (size_t)r * C;
#pragma unroll
    for (int i = 0; i < 4; i++) {
        int e = (lane + 32 * i) * 4;
        float4 g  = *(const float4*)(gamma + e);
        float4 be = *(const float4*)(beta + e);
        float f0 = (v[i].x - mu) * rs * g.x + be.x;
        float f1 = (v[i].y - mu) * rs * g.y + be.y;
        float f2 = (v[i].z - mu) * rs * g.z + be.z;
        float f3 = (v[i].w - mu) * rs * g.w + be.w;
        uint32_t lo0, lo1;
        uint32_t hi0 = pack_hi_lo(f0, f1, lo0);
        uint32_t hi1 = pack_hi_lo(f2, f3, lo1);
        *(uint2*)(dh + rb + e) = make_uint2(hi0, hi1);
        *(uint2*)(dl + rb + e) = make_uint2(lo0, lo1);
    }
}

// ---------------- kernel 2: pack weights hi/lo once ----------------
__global__ void pack_w_kernel(const float* __restrict__ Wq, const float* __restrict__ Wk,
                              const float* __restrict__ Wv) {
    size_t e = ((size_t)blockIdx.x * 256 + threadIdx.x) * 4;   // 4 floats/thread
    int z = (int)(e / ((size_t)C * C));
    size_t rem = e % ((size_t)C * C);
    const float* W = (z == 0) ? Wq : (z == 1) ? Wk : Wv;
    float4 w = *(const float4*)(W + rem);
    uint32_t lo0, lo1;
    uint32_t hi0 = pack_hi_lo(w.x, w.y, lo0);
    uint32_t hi1 = pack_hi_lo(w.z, w.w, lo1);
    *(uint2*)((__nv_bfloat16*)g_wh4 + e) = make_uint2(hi0, hi1);
    *(uint2*)((__nv_bfloat16*)g_wl4 + e) = make_uint2(lo0, lo1);
}

// ---------------- kernel 3: QKV GEMM (bf16 split mma.sync, cp.async double-buffer) ----
// BM=BN=128, BK=64. 8 warps 4(M)x2(N), warp tile 32x64.
// smem stage (64KB): Ah[16K] Al[16K] Bh[16K] Bl[16K]; 2 stages.
// row layout: 128B rows (64 bf16), 8x16B chunks, swizzle chunk^(row&7).
#define STG 65536

__device__ __forceinline__ void fill_stage(uint32_t s, int k0,
    const __nv_bfloat16* Ah_g, const __nv_bfloat16* Al_g,
    const __nv_bfloat16* Bh_g, const __nv_bfloat16* Bl_g,
    int r0, int o0, int tid) {
#pragma unroll
    for (int j = 0; j < 4; ++j) {
        int idx = j * 256 + tid;              // 0..1023
        int row = idx >> 3, c = idx & 7;
        uint32_t doff = (uint32_t)(row * 128 + ((c ^ (row & 7)) << 4));
        size_t ga = (size_t)(r0 + row) * C + k0 + c * 8;
        size_t gb = (size_t)(o0 + row) * C + k0 + c * 8;
        cp16(s + doff,         Ah_g + ga);
        cp16(s + 16384 + doff, Al_g + ga);
        cp16(s + 32768 + doff, Bh_g + gb);
        cp16(s + 49152 + doff, Bl_g + gb);
    }
}

__global__ __launch_bounds__(256, 1) void qkv_gemm_mma() {
    extern __shared__ char sm[];
    uint32_t sb = smem_u32(sm);
    int tid = threadIdx.x;
    int wid = tid >> 5, lane = tid & 31;
    int wm = wid & 3, wn = wid >> 2;

    int z = blockIdx.z;
    const __nv_bfloat16* Ah_g = (z == 0) ? (const __nv_bfloat16*)g_xh4 : (const __nv_bfloat16*)g_ch4;
    const __nv_bfloat16* Al_g = (z == 0) ? (const __nv_bfloat16*)g_xl4 : (const __nv_bfloat16*)g_cl4;
    const __nv_bfloat16* Bh_g = (const __nv_bfloat16*)g_wh4 + (size_t)z * C * C;
    const __nv_bfloat16* Bl_g = (const __nv_bfloat16*)g_wl4 + (size_t)z * C * C;
    float* dst = (z == 0) ? g_q : (z == 1) ? g_k : g_v;

    int r0 = blockIdx.y * 128;
    int o0 = blockIdx.x * 128;

    float acc[2][8][4];
#pragma unroll
    for (int i = 0; i < 2; i++)
#pragma unroll
        for (int j = 0; j < 8; j++)
#pragma unroll
            for (int q = 0; q < 4; q++) acc[i][j][q] = 0.f;

    int a_row   = wm * 32 + (lane & 15);
    int a_khalf = lane >> 4;
    int b_nrow  = wn * 64 + (lane & 7) + ((lane >> 4) << 3);
    int b_khalf = (lane >> 3) & 1;

    fill_stage(sb, 0, Ah_g, Al_g, Bh_g, Bl_g, r0, o0, tid);
    CP_COMMIT();

    for (int c = 0; c < 8; ++c) {   // 8 chunks of BK=64
        if (c < 7) {
            fill_stage(sb + ((c + 1) & 1) * STG, (c + 1) * 64,
                       Ah_g, Al_g, Bh_g, Bl_g, r0, o0, tid);
            CP_COMMIT();
            CP_WAIT1();
        } else {
            CP_WAIT0();
        }
        __syncthreads();

        uint32_t base = sb + (c & 1) * STG;
#pragma unroll
        for (int ks = 0; ks < 4; ++ks) {     // 4 x k16 inside BK=64
            uint32_t ah[2][4], al[2][4];
#pragma unroll
            for (int mt = 0; mt < 2; ++mt) {
                int row = a_row + mt * 16;
                int ch = ks * 2 + a_khalf;
                uint32_t off = (uint32_t)(row * 128 + ((ch ^ (row & 7)) << 4));
                ldsm_x4(ah[mt], base + off);
                ldsm_x4(al[mt], base + 16384 + off);
            }
#pragma unroll
            for (int ng = 0; ng < 4; ++ng) {
                int nr = b_nrow + ng * 16;
                int ch = ks * 2 + b_khalf;
                uint32_t off = (uint32_t)(nr * 128 + ((ch ^ (nr & 7)) << 4));
                uint32_t bh[4], bl[4];
                ldsm_x4(bh, base + 32768 + off);
                ldsm_x4(bl, base + 49152 + off);
#pragma unroll
                for (int mt = 0; mt < 2; ++mt)
#pragma unroll
                    for (int hf = 0; hf < 2; ++hf) {
                        float* cc = acc[mt][ng * 2 + hf];
                        mma16816(cc, ah[mt], bh[2 * hf], bh[2 * hf + 1]);
                        mma16816(cc, ah[mt], bl[2 * hf], bl[2 * hf + 1]);
                        mma16816(cc, al[mt], bh[2 * hf], bh[2 * hf + 1]);
                    }
            }
        }
        __syncthreads();
    }

    // ---- epilogue ----
    int qr = lane >> 2, qc = (lane & 3) * 2;
#pragma unroll
    for (int mt = 0; mt < 2; ++mt) {
        int row = r0 + wm * 32 + mt * 16 + qr;
#pragma unroll
        for (int nt = 0; nt < 8; ++nt) {
            int col = o0 + wn * 64 + nt * 8 + qc;
            float* cc = acc[mt][nt];
            *(float2*)(dst + (size_t)row * C + col)       = make_float2(cc[0], cc[1]);
            *(float2*)(dst + (size_t)(row + 8) * C + col) = make_float2(cc[2], cc[3]);
        }
    }
}

// ---------------- kernel 4: attention + residual + output transpose ----------------
__global__ __launch_bounds__(256, 1) void attn_kernel(const float* __restrict__ x,
                                                      float* __restrict__ out) {
    extern __shared__ float4 sm4[];
    float4* ks = sm4;
    float4* vs = sm4 + 256 * 16;

    int bi = blockIdx.x / H;
    int h  = blockIdx.x % H;
    size_t base = (size_t)bi * T * C + h * HD;
    const float4* kg = (const float4*)(g_k + base);
    const float4* vg = (const float4*)(g_v + base);
    int tid = threadIdx.x;

    for (int i = tid; i < 256 * 16; i += 256) {
        int r = i >> 4, c = i & 15;
        ks[i] = kg[(size_t)r * (C / 4) + c];
        vs[i] = vg[(size_t)r * (C / 4) + c];
    }
    __syncthreads();

    const float4* qg = (const float4*)(g_q + base + (size_t)tid * C);
    float4 q4[16];
#pragma unroll
    for (int i = 0; i < 16; i++) q4[i] = qg[i];

    float4 a4[16];
#pragma unroll
    for (int i = 0; i < 16; i++) a4[i] = make_float4(0.f, 0.f, 0.f, 0.f);
    float ssum = 0.f;

    for (int m = 0; m < 256; m++) {
        const float4* kr = ks + m * 16;
        float p0 = 0.f, p1 = 0.f, p2 = 0.f, p3 = 0.f;
#pragma unroll
        for (int i = 0; i < 16; i++) {
            float4 kv = kr[i];
            p0 += q4[i].x * kv.x;
            p1 += q4[i].y * kv.y;
            p2 += q4[i].z * kv.z;
            p3 += q4[i].w * kv.w;
        }
        float s = ((p0 + p1) + (p2 + p3)) * 0.125f;
        float e = __expf(s);
        ssum += e;
        const float4* vr = vs + m * 16;
#pragma unroll
        for (int i = 0; i < 16; i++) {
            float4 vv = vr[i];
            a4[i].x += e * vv.x;
            a4[i].y += e * vv.y;
            a4[i].z += e * vv.z;
            a4[i].w += e * vv.w;
        }
    }
    float inv = 1.0f / ssum;

    int bb = bi / NJ, n = bi % NJ;
    size_t oo = ((size_t)(bb * T + tid) * NJ + n) * C + h * HD;
    const float4* xg = (const float4*)(x + oo);
    float4* og = (float4*)(out + oo);
#pragma unroll
    for (int i = 0; i < 16; i++) {
        float4 xv = xg[i];
        og[i] = make_float4(xv.x + a4[i].x * inv, xv.y + a4[i].y * inv,
                            xv.z + a4[i].z * inv, xv.w + a4[i].w * inv);
    }
}

// ---------------- launch ----------------
extern "C" void kernel_launch(void* const* d_in, const int* in_sizes, int n_in,
                              void* d_out, int out_size) {
    const float* x     = (const float*)d_in[0];
    const float* cx    = (const float*)d_in[1];
    const float* gamma = (const float*)d_in[2];
    const float* beta  = (const float*)d_in[3];
    const float* Wq    = (const float*)d_in[4];
    const float* Wk    = (const float*)d_in[5];
    const float* Wv    = (const float*)d_in[6];
    float* out = (float*)d_out;

    cudaFuncSetAttribute(qkv_gemm_mma, cudaFuncAttributeMaxDynamicSharedMemorySize, 2 * STG);
    cudaFuncSetAttribute(attn_kernel, cudaFuncAttributeMaxDynamicSharedMemorySize, 131072);

    ln_pack_kernel<<<2 * RTOT / 8, 256>>>(x, cx, gamma, beta);
    pack_w_kernel<<<3 * C * C / 1024, 256>>>(Wq, Wk, Wv);

    dim3 gg(C / 128, RTOT / 128, 3);
    qkv_gemm_mma<<<gg, 256, 2 * STG>>>();

    attn_kernel<<<BATCH * H, 256, 131072>>>(x, out);
}

// round 9
// speedup vs baseline: 3.2701x; 1.6708x over previous
#include <cuda_runtime.h>
#include <cuda_bf16.h>
#include <cstdint>

#define Bb    16
#define T     256
#define NJ    24
#define C     512
#define H     8
#define HD    64
#define BATCH (Bb*NJ)     // 384
#define RTOT  (BATCH*T)   // 98304

// ---------------- scratch (static device memory; no allocations) ----------------
// packed bf16 hi/lo operands (uint4 => 16B alignment for cp.async)
__device__ uint4 g_xh4[(size_t)RTOT * C / 8];
__device__ uint4 g_xl4[(size_t)RTOT * C / 8];
__device__ uint4 g_ch4[(size_t)RTOT * C / 8];
__device__ uint4 g_cl4[(size_t)RTOT * C / 8];
__device__ uint4 g_wh4[(size_t)3 * C * C / 8];
__device__ uint4 g_wl4[(size_t)3 * C * C / 8];
// qkv outputs as bf16 hi/lo
__device__ uint4 g_qh4[(size_t)RTOT * C / 8];
__device__ uint4 g_ql4[(size_t)RTOT * C / 8];
__device__ uint4 g_kh4[(size_t)RTOT * C / 8];
__device__ uint4 g_kl4[(size_t)RTOT * C / 8];
__device__ uint4 g_vh4[(size_t)RTOT * C / 8];
__device__ uint4 g_vl4[(size_t)RTOT * C / 8];

// ---------------- helpers ----------------
__device__ __forceinline__ uint32_t smem_u32(const void* p) {
    uint32_t a;
    asm("{ .reg .u64 t; cvta.to.shared.u64 t, %1; cvt.u32.u64 %0, t; }" : "=r"(a) : "l"(p));
    return a;
}
__device__ __forceinline__ void cp16(uint32_t dst, const void* src) {
    asm volatile("cp.async.cg.shared.global [%0], [%1], 16;" :: "r"(dst), "l"(src));
}
#define CP_COMMIT() asm volatile("cp.async.commit_group;" ::: "memory")
#define CP_WAIT2()  asm volatile("cp.async.wait_group 2;" ::: "memory")
#define CP_WAIT0()  asm volatile("cp.async.wait_group 0;" ::: "memory")

__device__ __forceinline__ void ldsm_x4(uint32_t* r, uint32_t addr) {
    asm volatile("ldmatrix.sync.aligned.m8n8.x4.shared.b16 {%0,%1,%2,%3}, [%4];"
                 : "=r"(r[0]), "=r"(r[1]), "=r"(r[2]), "=r"(r[3]) : "r"(addr));
}
__device__ __forceinline__ void ldsm_x4_t(uint32_t* r, uint32_t addr) {
    asm volatile("ldmatrix.sync.aligned.m8n8.x4.trans.shared.b16 {%0,%1,%2,%3}, [%4];"
                 : "=r"(r[0]), "=r"(r[1]), "=r"(r[2]), "=r"(r[3]) : "r"(addr));
}
__device__ __forceinline__ void mma16816(float* c, const uint32_t* a,
                                         uint32_t b0, uint32_t b1) {
    asm volatile("mma.sync.aligned.m16n8k16.row.col.f32.bf16.bf16.f32 "
                 "{%0,%1,%2,%3}, {%4,%5,%6,%7}, {%8,%9}, {%0,%1,%2,%3};"
                 : "+f"(c[0]), "+f"(c[1]), "+f"(c[2]), "+f"(c[3])
                 : "r"(a[0]), "r"(a[1]), "r"(a[2]), "r"(a[3]), "r"(b0), "r"(b1));
}
__device__ __forceinline__ uint32_t pack_hi_lo(float f0, float f1, uint32_t& lo) {
    __nv_bfloat16 a = __float2bfloat16(f0);
    __nv_bfloat16 b = __float2bfloat16(f1);
    __nv_bfloat162 hp(a, b);
    __nv_bfloat162 lp(__float2bfloat16(f0 - __bfloat162float(a)),
                      __float2bfloat16(f1 - __bfloat162float(b)));
    lo = *reinterpret_cast<uint32_t*>(&lp);
    return *reinterpret_cast<uint32_t*>(&hp);
}

// ---------------- kernel 1: LN stats + apply + bf16 hi/lo pack ----------------
__global__ void ln_pack_kernel(const float* __restrict__ x, const float* __restrict__ cx,
                               const float* __restrict__ gamma, const float* __restrict__ beta) {
    int warp = threadIdx.x >> 5, lane = threadIdx.x & 31;
    int row = blockIdx.x * 8 + warp;
    const float* src = (row < RTOT) ? x : cx;
    int r  = (row < RTOT) ? row : row - RTOT;
    int bidx = r >> 8;
    int t    = r & 255;
    int bb = bidx / NJ, n = bidx % NJ;
    const float4* p = (const float4*)(src + ((size_t)(bb * T + t) * NJ + n) * C);
    float4 v[4];
    float s = 0.f, sq = 0.f;
#pragma unroll
    for (int i = 0; i < 4; i++) {
        v[i] = p[lane + 32 * i];
        s  += v[i].x + v[i].y + v[i].z + v[i].w;
        sq += v[i].x * v[i].x + v[i].y * v[i].y + v[i].z * v[i].z + v[i].w * v[i].w;
    }
#pragma unroll
    for (int o = 16; o; o >>= 1) {
        s  += __shfl_xor_sync(0xffffffffu, s, o);
        sq += __shfl_xor_sync(0xffffffffu, sq, o);
    }
    float mu = s * (1.0f / C);
    float rs = rsqrtf(sq * (1.0f / C) - mu * mu + 1e-5f);

    __nv_bfloat16* dh = (row < RTOT) ? (__nv_bfloat16*)g_xh4 : (__nv_bfloat16*)g_ch4;
    __nv_bfloat16* dl = (row < RTOT) ? (__nv_bfloat16*)g_xl4 : (__nv_bfloat16*)g_cl4;
    size_t rb = (size_t)r * C;
#pragma unroll
    for (int i = 0; i < 4; i++) {
        int e = (lane + 32 * i) * 4;
        float4 g  = *(const float4*)(gamma + e);
        float4 be = *(const float4*)(beta + e);
        float f0 = (v[i].x - mu) * rs * g.x + be.x;
        float f1 = (v[i].y - mu) * rs * g.y + be.y;
        float f2 = (v[i].z - mu) * rs * g.z + be.z;
        float f3 = (v[i].w - mu) * rs * g.w + be.w;
        uint32_t lo0, lo1;
        uint32_t hi0 = pack_hi_lo(f0, f1, lo0);
        uint32_t hi1 = pack_hi_lo(f2, f3, lo1);
        *(uint2*)(dh + rb + e) = make_uint2(hi0, hi1);
        *(uint2*)(dl + rb + e) = make_uint2(lo0, lo1);
    }
}

// ---------------- kernel 2: pack weights hi/lo ----------------
__global__ void pack_w_kernel(const float* __restrict__ Wq, const float* __restrict__ Wk,
                              const float* __restrict__ Wv) {
    size_t e = ((size_t)blockIdx.x * 256 + threadIdx.x) * 4;
    int z = (int)(e / ((size_t)C * C));
    size_t rem = e % ((size_t)C * C);
    const float* W = (z == 0) ? Wq : (z == 1) ? Wk : Wv;
    float4 w = *(const float4*)(W + rem);
    uint32_t lo0, lo1;
    uint32_t hi0 = pack_hi_lo(w.x, w.y, lo0);
    uint32_t hi1 = pack_hi_lo(w.z, w.w, lo1);
    *(uint2*)((__nv_bfloat16*)g_wh4 + e) = make_uint2(hi0, hi1);
    *(uint2*)((__nv_bfloat16*)g_wl4 + e) = make_uint2(lo0, lo1);
}

// ---------------- kernel 3: QKV GEMM, bf16 split mma, BK=32, 4-stage cp.async ----
// stage = 32KB: Ah[8K] Al[8K] Bh[8K] Bl[8K]; tiles 128 rows x 64B (4x16B chunks),
// swizzle chunk ^ ((row>>1)&3).
#define QSTG 32768

__device__ __forceinline__ void qfill(uint32_t s, int k0,
    const __nv_bfloat16* Ah_g, const __nv_bfloat16* Al_g,
    const __nv_bfloat16* Bh_g, const __nv_bfloat16* Bl_g,
    int r0, int o0, int tid) {
#pragma unroll
    for (int j = 0; j < 2; ++j) {
        int idx = j * 256 + tid;              // 0..511
        int row = idx >> 2, c = idx & 3;
        uint32_t doff = (uint32_t)(row * 64 + ((c ^ ((row >> 1) & 3)) << 4));
        size_t ga = (size_t)(r0 + row) * C + k0 + c * 8;
        size_t gb = (size_t)(o0 + row) * C + k0 + c * 8;
        cp16(s + doff,         Ah_g + ga);
        cp16(s + 8192  + doff, Al_g + ga);
        cp16(s + 16384 + doff, Bh_g + gb);
        cp16(s + 24576 + doff, Bl_g + gb);
    }
}

__global__ __launch_bounds__(256, 1) void qkv_gemm_mma() {
    extern __shared__ char sm[];
    uint32_t sb = smem_u32(sm);
    int tid = threadIdx.x;
    int wid = tid >> 5, lane = tid & 31;
    int wm = wid & 3, wn = wid >> 2;

    int z = blockIdx.z;
    const __nv_bfloat16* Ah_g = (z == 0) ? (const __nv_bfloat16*)g_xh4 : (const __nv_bfloat16*)g_ch4;
    const __nv_bfloat16* Al_g = (z == 0) ? (const __nv_bfloat16*)g_xl4 : (const __nv_bfloat16*)g_cl4;
    const __nv_bfloat16* Bh_g = (const __nv_bfloat16*)g_wh4 + (size_t)z * C * C;
    const __nv_bfloat16* Bl_g = (const __nv_bfloat16*)g_wl4 + (size_t)z * C * C;
    __nv_bfloat16* dh = (__nv_bfloat16*)((z == 0) ? g_qh4 : (z == 1) ? g_kh4 : g_vh4);
    __nv_bfloat16* dl = (__nv_bfloat16*)((z == 0) ? g_ql4 : (z == 1) ? g_kl4 : g_vl4);

    int r0 = blockIdx.y * 128;
    int o0 = blockIdx.x * 128;

    float acc[2][8][4];
#pragma unroll
    for (int i = 0; i < 2; i++)
#pragma unroll
        for (int j = 0; j < 8; j++)
#pragma unroll
            for (int q = 0; q < 4; q++) acc[i][j][q] = 0.f;

    int a_row   = wm * 32 + (lane & 15);
    int a_khalf = lane >> 4;
    int b_nrow  = wn * 64 + (lane & 7) + ((lane >> 4) << 3);
    int b_khalf = (lane >> 3) & 1;

    qfill(sb,            0,  Ah_g, Al_g, Bh_g, Bl_g, r0, o0, tid); CP_COMMIT();
    qfill(sb + QSTG,     32, Ah_g, Al_g, Bh_g, Bl_g, r0, o0, tid); CP_COMMIT();
    qfill(sb + 2 * QSTG, 64, Ah_g, Al_g, Bh_g, Bl_g, r0, o0, tid); CP_COMMIT();

    for (int c = 0; c < 16; ++c) {       // 16 chunks of BK=32
        CP_WAIT2();
        __syncthreads();
        if (c + 3 < 16) {
            qfill(sb + ((c + 3) & 3) * QSTG, (c + 3) * 32,
                  Ah_g, Al_g, Bh_g, Bl_g, r0, o0, tid);
        }
        CP_COMMIT();   // commit every iter to keep group counting uniform

        uint32_t base = sb + (c & 3) * QSTG;
#pragma unroll
        for (int ks = 0; ks < 2; ++ks) {
            uint32_t ah[2][4], al[2][4];
#pragma unroll
            for (int mt = 0; mt < 2; ++mt) {
                int row = a_row + mt * 16;
                int ch = ks * 2 + a_khalf;
                uint32_t off = (uint32_t)(row * 64 + ((ch ^ ((row >> 1) & 3)) << 4));
                ldsm_x4(ah[mt], base + off);
                ldsm_x4(al[mt], base + 8192 + off);
            }
            uint32_t bh[4][4], bl[4][4];
#pragma unroll
            for (int ng = 0; ng < 4; ++ng) {
                int nr = b_nrow + ng * 16;
                int ch = ks * 2 + b_khalf;
                uint32_t off = (uint32_t)(nr * 64 + ((ch ^ ((nr >> 1) & 3)) << 4));
                ldsm_x4(bh[ng], base + 16384 + off);
                ldsm_x4(bl[ng], base + 24576 + off);
            }
            // product-major sweeps: consecutive mma hit distinct accumulators
#pragma unroll
            for (int mt = 0; mt < 2; ++mt)
#pragma unroll
                for (int ng = 0; ng < 4; ++ng)
#pragma unroll
                    for (int hf = 0; hf < 2; ++hf)
                        mma16816(acc[mt][ng * 2 + hf], ah[mt], bh[ng][2 * hf], bh[ng][2 * hf + 1]);
#pragma unroll
            for (int mt = 0; mt < 2; ++mt)
#pragma unroll
                for (int ng = 0; ng < 4; ++ng)
#pragma unroll
                    for (int hf = 0; hf < 2; ++hf)
                        mma16816(acc[mt][ng * 2 + hf], ah[mt], bl[ng][2 * hf], bl[ng][2 * hf + 1]);
#pragma unroll
            for (int mt = 0; mt < 2; ++mt)
#pragma unroll
                for (int ng = 0; ng < 4; ++ng)
#pragma unroll
                    for (int hf = 0; hf < 2; ++hf)
                        mma16816(acc[mt][ng * 2 + hf], al[mt], bh[ng][2 * hf], bh[ng][2 * hf + 1]);
        }
        __syncthreads();
    }

    // ---- epilogue: split fp32 acc -> bf16 hi/lo, store packed pairs ----
    int qr = lane >> 2, qc = (lane & 3) * 2;
#pragma unroll
    for (int mt = 0; mt < 2; ++mt) {
        int row = r0 + wm * 32 + mt * 16 + qr;
#pragma unroll
        for (int nt = 0; nt < 8; ++nt) {
            int col = o0 + wn * 64 + nt * 8 + qc;
            float* cc = acc[mt][nt];
            uint32_t l0, l1;
            uint32_t h0 = pack_hi_lo(cc[0], cc[1], l0);
            uint32_t h1 = pack_hi_lo(cc[2], cc[3], l1);
            *(uint32_t*)(dh + (size_t)row * C + col)       = h0;
            *(uint32_t*)(dl + (size_t)row * C + col)       = l0;
            *(uint32_t*)(dh + (size_t)(row + 8) * C + col) = h1;
            *(uint32_t*)(dl + (size_t)(row + 8) * C + col) = l1;
        }
    }
}

// ---------------- kernel 4: attention via mma.sync (bf16 split) ----------------
// block = (bi, h); 8 warps; warp w owns query rows [32w, 32w+32).
// smem: QH[32K] QL[32K] KH[32K] KL[32K] VH[32K] VL[32K] = 192KB.
// K/V/Q rows: 64 bf16 = 128B, 8x16B chunks, swizzle chunk^(row&7).
#define AQH 0
#define AQL 32768
#define AKH 65536
#define AKL 98304
#define AVH 131072
#define AVL 163840
#define ATT_SMEM 196608

__global__ __launch_bounds__(256, 1) void attn_mma(const float* __restrict__ x,
                                                   float* __restrict__ out) {
    extern __shared__ char sm[];
    uint32_t sb = smem_u32(sm);
    int tid = threadIdx.x;
    int wid = tid >> 5, lane = tid & 31;

    int bi = blockIdx.x / H;
    int h  = blockIdx.x % H;
    size_t rbase = (size_t)bi * T;

    const __nv_bfloat16* qh_g = (const __nv_bfloat16*)g_qh4;
    const __nv_bfloat16* ql_g = (const __nv_bfloat16*)g_ql4;
    const __nv_bfloat16* kh_g = (const __nv_bfloat16*)g_kh4;
    const __nv_bfloat16* kl_g = (const __nv_bfloat16*)g_kl4;
    const __nv_bfloat16* vh_g = (const __nv_bfloat16*)g_vh4;
    const __nv_bfloat16* vl_g = (const __nv_bfloat16*)g_vl4;

    // fill K/V (whole block): 256 rows x 8 chunks
    for (int i = tid; i < 2048; i += 256) {
        int r = i >> 3, c = i & 7;
        uint32_t off = (uint32_t)(r * 128 + ((c ^ (r & 7)) << 4));
        size_t ga = (rbase + r) * C + h * HD + c * 8;
        cp16(sb + AKH + off, kh_g + ga);
        cp16(sb + AKL + off, kl_g + ga);
        cp16(sb + AVH + off, vh_g + ga);
        cp16(sb + AVL + off, vl_g + ga);
    }
    // fill Q (per-warp region): 32 rows x 8 chunks
    for (int i = lane; i < 256; i += 32) {
        int r = i >> 3, c = i & 7;
        uint32_t off = (uint32_t)(wid * 4096 + r * 128 + ((c ^ (r & 7)) << 4));
        size_t ga = (rbase + wid * 32 + r) * C + h * HD + c * 8;
        cp16(sb + AQH + off, qh_g + ga);
        cp16(sb + AQL + off, ql_g + ga);
    }
    CP_COMMIT();
    CP_WAIT0();
    __syncthreads();

    float yacc[2][8][4];
#pragma unroll
    for (int i = 0; i < 2; i++)
#pragma unroll
        for (int j = 0; j < 8; j++)
#pragma unroll
            for (int q = 0; q < 4; q++) yacc[i][j][q] = 0.f;
    float rs[2][2] = {{0.f, 0.f}, {0.f, 0.f}};

    uint32_t qbase = sb + (uint32_t)(wid * 4096);

    for (int nb = 0; nb < 4; ++nb) {         // key blocks of 64
        float sacc[2][8][4];
#pragma unroll
        for (int i = 0; i < 2; i++)
#pragma unroll
            for (int j = 0; j < 8; j++)
#pragma unroll
                for (int q = 0; q < 4; q++) sacc[i][j][q] = 0.f;

        // ---- S = Q K^T over hd (4 k16 steps) ----
#pragma unroll
        for (int kt = 0; kt < 4; ++kt) {
            uint32_t ah[2][4], al[2][4];
#pragma unroll
            for (int mt = 0; mt < 2; ++mt) {
                int row = mt * 16 + (lane & 15);
                int ch = kt * 2 + (lane >> 4);
                uint32_t off = (uint32_t)(row * 128 + ((ch ^ (row & 7)) << 4));
                ldsm_x4(ah[mt], qbase + AQH + off);
                ldsm_x4(al[mt], qbase + AQL + off);
            }
            uint32_t kbh[4][4], kbl[4][4];
#pragma unroll
            for (int ng = 0; ng < 4; ++ng) {
                int nr = nb * 64 + ng * 16 + (lane & 7) + ((lane >> 4) << 3);
                int ch = kt * 2 + ((lane >> 3) & 1);
                uint32_t off = (uint32_t)(nr * 128 + ((ch ^ (nr & 7)) << 4));
                ldsm_x4(kbh[ng], sb + AKH + off);
                ldsm_x4(kbl[ng], sb + AKL + off);
            }
#pragma unroll
            for (int mt = 0; mt < 2; ++mt)
#pragma unroll
                for (int ng = 0; ng < 4; ++ng)
#pragma unroll
                    for (int hf = 0; hf < 2; ++hf)
                        mma16816(sacc[mt][ng * 2 + hf], ah[mt], kbh[ng][2 * hf], kbh[ng][2 * hf + 1]);
#pragma unroll
            for (int mt = 0; mt < 2; ++mt)
#pragma unroll
                for (int ng = 0; ng < 4; ++ng)
#pragma unroll
                    for (int hf = 0; hf < 2; ++hf)
                        mma16816(sacc[mt][ng * 2 + hf], ah[mt], kbl[ng][2 * hf], kbl[ng][2 * hf + 1]);
#pragma unroll
            for (int mt = 0; mt < 2; ++mt)
#pragma unroll
                for (int ng = 0; ng < 4; ++ng)
#pragma unroll
                    for (int hf = 0; hf < 2; ++hf)
                        mma16816(sacc[mt][ng * 2 + hf], al[mt], kbh[ng][2 * hf], kbh[ng][2 * hf + 1]);
        }

        // ---- E = exp(S/8); accumulate row sums ----
#pragma unroll
        for (int mt = 0; mt < 2; ++mt)
#pragma unroll
            for (int nt = 0; nt < 8; ++nt) {
                float* cc = sacc[mt][nt];
                cc[0] = __expf(cc[0] * 0.125f);
                cc[1] = __expf(cc[1] * 0.125f);
                cc[2] = __expf(cc[2] * 0.125f);
                cc[3] = __expf(cc[3] * 0.125f);
                rs[mt][0] += cc[0] + cc[1];
                rs[mt][1] += cc[2] + cc[3];
            }

        // ---- Y += P V : per k16 step j over the 64 keys ----
#pragma unroll
        for (int j = 0; j < 4; ++j) {
            // A-frags from E (C->A fragment identity), hi + lo
            uint32_t pah[2][4], pal[2][4];
#pragma unroll
            for (int mt = 0; mt < 2; ++mt) {
                pah[mt][0] = pack_hi_lo(sacc[mt][2 * j][0],     sacc[mt][2 * j][1],     pal[mt][0]);
                pah[mt][1] = pack_hi_lo(sacc[mt][2 * j][2],     sacc[mt][2 * j][3],     pal[mt][1]);
                pah[mt][2] = pack_hi_lo(sacc[mt][2 * j + 1][0], sacc[mt][2 * j + 1][1], pal[mt][2]);
                pah[mt][3] = pack_hi_lo(sacc[mt][2 * j + 1][2], sacc[mt][2 * j + 1][3], pal[mt][3]);
            }
            // V B-frags via ldmatrix.trans ([key][hd] -> [hd][key])
            uint32_t vbh[4][4], vbl[4][4];
#pragma unroll
            for (int hdt = 0; hdt < 4; ++hdt) {
                int vr = nb * 64 + j * 16 + (lane & 7) + (((lane >> 3) & 1) << 3);
                int ch = hdt * 2 + (lane >> 4);
                uint32_t off = (uint32_t)(vr * 128 + ((ch ^ (vr & 7)) << 4));
                ldsm_x4_t(vbh[hdt], sb + AVH + off);
                ldsm_x4_t(vbl[hdt], sb + AVL + off);
            }
#pragma unroll
            for (int mt = 0; mt < 2; ++mt)
#pragma unroll
                for (int hdt = 0; hdt < 4; ++hdt)
#pragma unroll
                    for (int hf = 0; hf < 2; ++hf)
                        mma16816(yacc[mt][hdt * 2 + hf], pah[mt], vbh[hdt][2 * hf], vbh[hdt][2 * hf + 1]);
#pragma unroll
            for (int mt = 0; mt < 2; ++mt)
#pragma unroll
                for (int hdt = 0; hdt < 4; ++hdt)
#pragma unroll
                    for (int hf = 0; hf < 2; ++hf)
                        mma16816(yacc[mt][hdt * 2 + hf], pah[mt], vbl[hdt][2 * hf], vbl[hdt][2 * hf + 1]);
#pragma unroll
            for (int mt = 0; mt < 2; ++mt)
#pragma unroll
                for (int hdt = 0; hdt < 4; ++hdt)
#pragma unroll
                    for (int hf = 0; hf < 2; ++hf)
                        mma16816(yacc[mt][hdt * 2 + hf], pal[mt], vbh[hdt][2 * hf], vbh[hdt][2 * hf + 1]);
        }
    }

    // ---- row-sum reduce within quads, normalize, residual add, store ----
#pragma unroll
    for (int mt = 0; mt < 2; ++mt)
#pragma unroll
        for (int i = 0; i < 2; ++i) {
            rs[mt][i] += __shfl_xor_sync(0xffffffffu, rs[mt][i], 1);
            rs[mt][i] += __shfl_xor_sync(0xffffffffu, rs[mt][i], 2);
        }

    int qr = lane >> 2, qc = (lane & 3) * 2;
    int bb = bi / NJ, n = bi % NJ;
#pragma unroll
    for (int mt = 0; mt < 2; ++mt) {
        float inv0 = 1.0f / rs[mt][0];
        float inv1 = 1.0f / rs[mt][1];
        int t0 = wid * 32 + mt * 16 + qr;
#pragma unroll
        for (int nt = 0; nt < 8; ++nt) {
            int hd = nt * 8 + qc;
            float* cc = yacc[mt][nt];
            size_t a0 = ((size_t)(bb * T + t0) * NJ + n) * C + h * HD + hd;
            size_t a1 = ((size_t)(bb * T + t0 + 8) * NJ + n) * C + h * HD + hd;
            float2 x0 = *(const float2*)(x + a0);
            float2 x1 = *(const float2*)(x + a1);
            *(float2*)(out + a0) = make_float2(x0.x + cc[0] * inv0, x0.y + cc[1] * inv0);
            *(float2*)(out + a1) = make_float2(x1.x + cc[2] * inv1, x1.y + cc[3] * inv1);
        }
    }
}

// ---------------- launch ----------------
extern "C" void kernel_launch(void* const* d_in, const int* in_sizes, int n_in,
                              void* d_out, int out_size) {
    const float* x     = (const float*)d_in[0];
    const float* cx    = (const float*)d_in[1];
    const float* gamma = (const float*)d_in[2];
    const float* beta  = (const float*)d_in[3];
    const float* Wq    = (const float*)d_in[4];
    const float* Wk    = (const float*)d_in[5];
    const float* Wv    = (const float*)d_in[6];
    float* out = (float*)d_out;

    cudaFuncSetAttribute(qkv_gemm_mma, cudaFuncAttributeMaxDynamicSharedMemorySize, 4 * QSTG);
    cudaFuncSetAttribute(attn_mma, cudaFuncAttributeMaxDynamicSharedMemorySize, ATT_SMEM);

    ln_pack_kernel<<<2 * RTOT / 8, 256>>>(x, cx, gamma, beta);
    pack_w_kernel<<<3 * C * C / 1024, 256>>>(Wq, Wk, Wv);

    dim3 gg(C / 128, RTOT / 128, 3);
    qkv_gemm_mma<<<gg, 256, 4 * QSTG>>>();

    attn_mma<<<BATCH * H, 256, ATT_SMEM>>>(x, out);
}

// round 11
// speedup vs baseline: 4.4464x; 1.3597x over previous
#include <cuda_runtime.h>
#include <cuda_fp16.h>
#include <cstdint>

#define Bb    16
#define T     256
#define NJ    24
#define C     512
#define H     8
#define HD    64
#define BATCH (Bb*NJ)     // 384
#define RTOT  (BATCH*T)   // 98304

// ---------------- scratch (static device memory; no allocations) ----------------
// fp16 operands (uint4 => 16B alignment for cp.async); hi/lo split where needed
__device__ uint4 g_xh4[(size_t)RTOT * C / 8];
__device__ uint4 g_xl4[(size_t)RTOT * C / 8];
__device__ uint4 g_ch4[(size_t)RTOT * C / 8];
__device__ uint4 g_cl4[(size_t)RTOT * C / 8];
__device__ uint4 g_wh4[(size_t)3 * C * C / 8];      // W hi only
__device__ uint4 g_qh4[(size_t)RTOT * C / 8];
__device__ uint4 g_ql4[(size_t)RTOT * C / 8];
__device__ uint4 g_kh4[(size_t)RTOT * C / 8];       // k hi only
__device__ uint4 g_vh4[(size_t)RTOT * C / 8];       // v hi only

// ---------------- helpers ----------------
__device__ __forceinline__ uint32_t smem_u32(const void* p) {
    uint32_t a;
    asm("{ .reg .u64 t; cvta.to.shared.u64 t, %1; cvt.u32.u64 %0, t; }" : "=r"(a) : "l"(p));
    return a;
}
__device__ __forceinline__ void cp16(uint32_t dst, const void* src) {
    asm volatile("cp.async.cg.shared.global [%0], [%1], 16;" :: "r"(dst), "l"(src));
}
#define CP_COMMIT() asm volatile("cp.async.commit_group;" ::: "memory")
#define CP_WAIT2()  asm volatile("cp.async.wait_group 2;" ::: "memory")
#define CP_WAIT0()  asm volatile("cp.async.wait_group 0;" ::: "memory")

__device__ __forceinline__ void ldsm_x4(uint32_t* r, uint32_t addr) {
    asm volatile("ldmatrix.sync.aligned.m8n8.x4.shared.b16 {%0,%1,%2,%3}, [%4];"
                 : "=r"(r[0]), "=r"(r[1]), "=r"(r[2]), "=r"(r[3]) : "r"(addr));
}
__device__ __forceinline__ void ldsm_x4_t(uint32_t* r, uint32_t addr) {
    asm volatile("ldmatrix.sync.aligned.m8n8.x4.trans.shared.b16 {%0,%1,%2,%3}, [%4];"
                 : "=r"(r[0]), "=r"(r[1]), "=r"(r[2]), "=r"(r[3]) : "r"(addr));
}
__device__ __forceinline__ void mma16816(float* c, const uint32_t* a,
                                         uint32_t b0, uint32_t b1) {
    asm volatile("mma.sync.aligned.m16n8k16.row.col.f32.f16.f16.f32 "
                 "{%0,%1,%2,%3}, {%4,%5,%6,%7}, {%8,%9}, {%0,%1,%2,%3};"
                 : "+f"(c[0]), "+f"(c[1]), "+f"(c[2]), "+f"(c[3])
                 : "r"(a[0]), "r"(a[1]), "r"(a[2]), "r"(a[3]), "r"(b0), "r"(b1));
}
// pack two floats into fp16x2 hi and fp16x2 lo (residual)
__device__ __forceinline__ uint32_t pack_hi_lo(float f0, float f1, uint32_t& lo) {
    __half h0 = __float2half_rn(f0);
    __half h1 = __float2half_rn(f1);
    __half l0 = __float2half_rn(f0 - __half2float(h0));
    __half l1 = __float2half_rn(f1 - __half2float(h1));
    __half2 hp(h0, h1), lp(l0, l1);
    lo = *reinterpret_cast<uint32_t*>(&lp);
    return *reinterpret_cast<uint32_t*>(&hp);
}
__device__ __forceinline__ uint32_t pack_hi(float f0, float f1) {
    __half2 hp(__float2half_rn(f0), __float2half_rn(f1));
    return *reinterpret_cast<uint32_t*>(&hp);
}

// ---------------- kernel 1: LN stats + apply + fp16 hi/lo pack ----------------
__global__ void ln_pack_kernel(const float* __restrict__ x, const float* __restrict__ cx,
                               const float* __restrict__ gamma, const float* __restrict__ beta) {
    int warp = threadIdx.x >> 5, lane = threadIdx.x & 31;
    int row = blockIdx.x * 8 + warp;
    const float* src = (row < RTOT) ? x : cx;
    int r  = (row < RTOT) ? row : row - RTOT;
    int bidx = r >> 8;
    int t    = r & 255;
    int bb = bidx / NJ, n = bidx % NJ;
    const float4* p = (const float4*)(src + ((size_t)(bb * T + t) * NJ + n) * C);
    float4 v[4];
    float s = 0.f, sq = 0.f;
#pragma unroll
    for (int i = 0; i < 4; i++) {
        v[i] = p[lane + 32 * i];
        s  += v[i].x + v[i].y + v[i].z + v[i].w;
        sq += v[i].x * v[i].x + v[i].y * v[i].y + v[i].z * v[i].z + v[i].w * v[i].w;
    }
#pragma unroll
    for (int o = 16; o; o >>= 1) {
        s  += __shfl_xor_sync(0xffffffffu, s, o);
        sq += __shfl_xor_sync(0xffffffffu, sq, o);
    }
    float mu = s * (1.0f / C);
    float rs = rsqrtf(sq * (1.0f / C) - mu * mu + 1e-5f);

    __half* dh = (row < RTOT) ? (__half*)g_xh4 : (__half*)g_ch4;
    __half* dl = (row < RTOT) ? (__half*)g_xl4 : (__half*)g_cl4;
    size_t rb = (size_t)r * C;
#pragma unroll
    for (int i = 0; i < 4; i++) {
        int e = (lane + 32 * i) * 4;
        float4 g  = *(const float4*)(gamma + e);
        float4 be = *(const float4*)(beta + e);
        float f0 = (v[i].x - mu) * rs * g.x + be.x;
        float f1 = (v[i].y - mu) * rs * g.y + be.y;
        float f2 = (v[i].z - mu) * rs * g.z + be.z;
        float f3 = (v[i].w - mu) * rs * g.w + be.w;
        uint32_t lo0, lo1;
        uint32_t hi0 = pack_hi_lo(f0, f1, lo0);
        uint32_t hi1 = pack_hi_lo(f2, f3, lo1);
        *(uint2*)(dh + rb + e) = make_uint2(hi0, hi1);
        *(uint2*)(dl + rb + e) = make_uint2(lo0, lo1);
    }
}

// ---------------- kernel 2: pack weights fp16 hi ----------------
__global__ void pack_w_kernel(const float* __restrict__ Wq, const float* __restrict__ Wk,
                              const float* __restrict__ Wv) {
    size_t e = ((size_t)blockIdx.x * 256 + threadIdx.x) * 4;
    int z = (int)(e / ((size_t)C * C));
    size_t rem = e % ((size_t)C * C);
    const float* W = (z == 0) ? Wq : (z == 1) ? Wk : Wv;
    float4 w = *(const float4*)(W + rem);
    *(uint2*)((__half*)g_wh4 + e) = make_uint2(pack_hi(w.x, w.y), pack_hi(w.z, w.w));
}

// ---------------- kernel 3: QKV GEMM, fp16 2-product, BK=32, 4-stage cp.async ----
// stage = 24KB: Ah[8K] Al[8K] Bh[8K]; tiles 128 rows x 64B (4x16B chunks),
// swizzle chunk ^ ((row>>1)&3).
#define QSTG 24576

__device__ __forceinline__ void qfill(uint32_t s, int k0,
    const __half* Ah_g, const __half* Al_g, const __half* Bh_g,
    int r0, int o0, int tid) {
#pragma unroll
    for (int j = 0; j < 2; ++j) {
        int idx = j * 256 + tid;              // 0..511
        int row = idx >> 2, c = idx & 3;
        uint32_t doff = (uint32_t)(row * 64 + ((c ^ ((row >> 1) & 3)) << 4));
        size_t ga = (size_t)(r0 + row) * C + k0 + c * 8;
        size_t gb = (size_t)(o0 + row) * C + k0 + c * 8;
        cp16(s + doff,         Ah_g + ga);
        cp16(s + 8192  + doff, Al_g + ga);
        cp16(s + 16384 + doff, Bh_g + gb);
    }
}

__global__ __launch_bounds__(256, 1) void qkv_gemm_mma() {
    extern __shared__ char sm[];
    uint32_t sb = smem_u32(sm);
    int tid = threadIdx.x;
    int wid = tid >> 5, lane = tid & 31;
    int wm = wid & 3, wn = wid >> 2;

    int z = blockIdx.z;
    const __half* Ah_g = (z == 0) ? (const __half*)g_xh4 : (const __half*)g_ch4;
    const __half* Al_g = (z == 0) ? (const __half*)g_xl4 : (const __half*)g_cl4;
    const __half* Bh_g = (const __half*)g_wh4 + (size_t)z * C * C;

    int r0 = blockIdx.y * 128;
    int o0 = blockIdx.x * 128;

    float acc[2][8][4];
#pragma unroll
    for (int i = 0; i < 2; i++)
#pragma unroll
        for (int j = 0; j < 8; j++)
#pragma unroll
            for (int q = 0; q < 4; q++) acc[i][j][q] = 0.f;

    int a_row   = wm * 32 + (lane & 15);
    int a_khalf = lane >> 4;
    int b_nrow  = wn * 64 + (lane & 7) + ((lane >> 4) << 3);
    int b_khalf = (lane >> 3) & 1;

    qfill(sb,            0,  Ah_g, Al_g, Bh_g, r0, o0, tid); CP_COMMIT();
    qfill(sb + QSTG,     32, Ah_g, Al_g, Bh_g, r0, o0, tid); CP_COMMIT();
    qfill(sb + 2 * QSTG, 64, Ah_g, Al_g, Bh_g, r0, o0, tid); CP_COMMIT();

    for (int c = 0; c < 16; ++c) {       // 16 chunks of BK=32
        CP_WAIT2();
        __syncthreads();
        if (c + 3 < 16) {
            qfill(sb + ((c + 3) & 3) * QSTG, (c + 3) * 32, Ah_g, Al_g, Bh_g, r0, o0, tid);
        }
        CP_COMMIT();

        uint32_t base = sb + (c & 3) * QSTG;
#pragma unroll
        for (int ks = 0; ks < 2; ++ks) {
            uint32_t ah[2][4], al[2][4];
#pragma unroll
            for (int mt = 0; mt < 2; ++mt) {
                int row = a_row + mt * 16;
                int ch = ks * 2 + a_khalf;
                uint32_t off = (uint32_t)(row * 64 + ((ch ^ ((row >> 1) & 3)) << 4));
                ldsm_x4(ah[mt], base + off);
                ldsm_x4(al[mt], base + 8192 + off);
            }
            uint32_t bh[4][4];
#pragma unroll
            for (int ng = 0; ng < 4; ++ng) {
                int nr = b_nrow + ng * 16;
                int ch = ks * 2 + b_khalf;
                uint32_t off = (uint32_t)(nr * 64 + ((ch ^ ((nr >> 1) & 3)) << 4));
                ldsm_x4(bh[ng], base + 16384 + off);
            }
            // product-major sweeps: distinct accumulators between reuses
#pragma unroll
            for (int mt = 0; mt < 2; ++mt)
#pragma unroll
                for (int ng = 0; ng < 4; ++ng)
#pragma unroll
                    for (int hf = 0; hf < 2; ++hf)
                        mma16816(acc[mt][ng * 2 + hf], ah[mt], bh[ng][2 * hf], bh[ng][2 * hf + 1]);
#pragma unroll
            for (int mt = 0; mt < 2; ++mt)
#pragma unroll
                for (int ng = 0; ng < 4; ++ng)
#pragma unroll
                    for (int hf = 0; hf < 2; ++hf)
                        mma16816(acc[mt][ng * 2 + hf], al[mt], bh[ng][2 * hf], bh[ng][2 * hf + 1]);
        }
        __syncthreads();
    }

    // ---- epilogue: q -> hi+lo; k,v -> hi only ----
    int qr = lane >> 2, qc = (lane & 3) * 2;
#pragma unroll
    for (int mt = 0; mt < 2; ++mt) {
        int row = r0 + wm * 32 + mt * 16 + qr;
#pragma unroll
        for (int nt = 0; nt < 8; ++nt) {
            int col = o0 + wn * 64 + nt * 8 + qc;
            float* cc = acc[mt][nt];
            if (z == 0) {
                uint32_t l0, l1;
                uint32_t h0 = pack_hi_lo(cc[0], cc[1], l0);
                uint32_t h1 = pack_hi_lo(cc[2], cc[3], l1);
                __half* dh = (__half*)g_qh4;
                __half* dl = (__half*)g_ql4;
                *(uint32_t*)(dh + (size_t)row * C + col)       = h0;
                *(uint32_t*)(dl + (size_t)row * C + col)       = l0;
                *(uint32_t*)(dh + (size_t)(row + 8) * C + col) = h1;
                *(uint32_t*)(dl + (size_t)(row + 8) * C + col) = l1;
            } else {
                __half* dh = (z == 1) ? (__half*)g_kh4 : (__half*)g_vh4;
                *(uint32_t*)(dh + (size_t)row * C + col)       = pack_hi(cc[0], cc[1]);
                *(uint32_t*)(dh + (size_t)(row + 8) * C + col) = pack_hi(cc[2], cc[3]);
            }
        }
    }
}

// ---------------- kernel 4: attention via mma.sync (fp16 2-product) ----------------
// block = (bi, h); 8 warps; warp w owns query rows [32w, 32w+32).
// smem: QH[32K] QL[32K] KH[32K] VH[32K] = 128KB.
// rows: 64 fp16 = 128B, 8x16B chunks, swizzle chunk^(row&7).
#define AQH 0
#define AQL 32768
#define AKH 65536
#define AVH 98304
#define ATT_SMEM 131072

__global__ __launch_bounds__(256, 1) void attn_mma(const float* __restrict__ x,
                                                   float* __restrict__ out) {
    extern __shared__ char sm[];
    uint32_t sb = smem_u32(sm);
    int tid = threadIdx.x;
    int wid = tid >> 5, lane = tid & 31;

    int bi = blockIdx.x / H;
    int h  = blockIdx.x % H;
    size_t rbase = (size_t)bi * T;

    const __half* qh_g = (const __half*)g_qh4;
    const __half* ql_g = (const __half*)g_ql4;
    const __half* kh_g = (const __half*)g_kh4;
    const __half* vh_g = (const __half*)g_vh4;

    // fill K/V (whole block): 256 rows x 8 chunks
    for (int i = tid; i < 2048; i += 256) {
        int r = i >> 3, c = i & 7;
        uint32_t off = (uint32_t)(r * 128 + ((c ^ (r & 7)) << 4));
        size_t ga = (rbase + r) * C + h * HD + c * 8;
        cp16(sb + AKH + off, kh_g + ga);
        cp16(sb + AVH + off, vh_g + ga);
    }
    // fill Q (per-warp region): 32 rows x 8 chunks
    for (int i = lane; i < 256; i += 32) {
        int r = i >> 3, c = i & 7;
        uint32_t off = (uint32_t)(wid * 4096 + r * 128 + ((c ^ (r & 7)) << 4));
        size_t ga = (rbase + wid * 32 + r) * C + h * HD + c * 8;
        cp16(sb + AQH + off, qh_g + ga);
        cp16(sb + AQL + off, ql_g + ga);
    }
    CP_COMMIT();
    CP_WAIT0();
    __syncthreads();

    float yacc[2][8][4];
#pragma unroll
    for (int i = 0; i < 2; i++)
#pragma unroll
        for (int j = 0; j < 8; j++)
#pragma unroll
            for (int q = 0; q < 4; q++) yacc[i][j][q] = 0.f;
    float rs[2][2] = {{0.f, 0.f}, {0.f, 0.f}};

    uint32_t qbase = sb + (uint32_t)(wid * 4096);

    for (int nb = 0; nb < 4; ++nb) {         // key blocks of 64
        float sacc[2][8][4];
#pragma unroll
        for (int i = 0; i < 2; i++)
#pragma unroll
            for (int j = 0; j < 8; j++)
#pragma unroll
                for (int q = 0; q < 4; q++) sacc[i][j][q] = 0.f;

        // ---- S = (Qh+Ql) Kh^T over hd (4 k16 steps) ----
#pragma unroll
        for (int kt = 0; kt < 4; ++kt) {
            uint32_t ah[2][4], al[2][4];
#pragma unroll
            for (int mt = 0; mt < 2; ++mt) {
                int row = mt * 16 + (lane & 15);
                int ch = kt * 2 + (lane >> 4);
                uint32_t off = (uint32_t)(row * 128 + ((ch ^ (row & 7)) << 4));
                ldsm_x4(ah[mt], qbase + AQH + off);
                ldsm_x4(al[mt], qbase + AQL + off);
            }
            uint32_t kbh[4][4];
#pragma unroll
            for (int ng = 0; ng < 4; ++ng) {
                int nr = nb * 64 + ng * 16 + (lane & 7) + ((lane >> 4) << 3);
                int ch = kt * 2 + ((lane >> 3) & 1);
                uint32_t off = (uint32_t)(nr * 128 + ((ch ^ (nr & 7)) << 4));
                ldsm_x4(kbh[ng], sb + AKH + off);
            }
#pragma unroll
            for (int mt = 0; mt < 2; ++mt)
#pragma unroll
                for (int ng = 0; ng < 4; ++ng)
#pragma unroll
                    for (int hf = 0; hf < 2; ++hf)
                        mma16816(sacc[mt][ng * 2 + hf], ah[mt], kbh[ng][2 * hf], kbh[ng][2 * hf + 1]);
#pragma unroll
            for (int mt = 0; mt < 2; ++mt)
#pragma unroll
                for (int ng = 0; ng < 4; ++ng)
#pragma unroll
                    for (int hf = 0; hf < 2; ++hf)
                        mma16816(sacc[mt][ng * 2 + hf], al[mt], kbh[ng][2 * hf], kbh[ng][2 * hf + 1]);
        }

        // ---- E = exp(S/8); accumulate row sums ----
#pragma unroll
        for (int mt = 0; mt < 2; ++mt)
#pragma unroll
            for (int nt = 0; nt < 8; ++nt) {
                float* cc = sacc[mt][nt];
                cc[0] = __expf(cc[0] * 0.125f);
                cc[1] = __expf(cc[1] * 0.125f);
                cc[2] = __expf(cc[2] * 0.125f);
                cc[3] = __expf(cc[3] * 0.125f);
                rs[mt][0] += cc[0] + cc[1];
                rs[mt][1] += cc[2] + cc[3];
            }

        // ---- Y += (Ph+Pl) Vh : per k16 step j over the 64 keys ----
#pragma unroll
        for (int j = 0; j < 4; ++j) {
            uint32_t pah[2][4], pal[2][4];
#pragma unroll
            for (int mt = 0; mt < 2; ++mt) {
                pah[mt][0] = pack_hi_lo(sacc[mt][2 * j][0],     sacc[mt][2 * j][1],     pal[mt][0]);
                pah[mt][1] = pack_hi_lo(sacc[mt][2 * j][2],     sacc[mt][2 * j][3],     pal[mt][1]);
                pah[mt][2] = pack_hi_lo(sacc[mt][2 * j + 1][0], sacc[mt][2 * j + 1][1], pal[mt][2]);
                pah[mt][3] = pack_hi_lo(sacc[mt][2 * j + 1][2], sacc[mt][2 * j + 1][3], pal[mt][3]);
            }
            uint32_t vbh[4][4];
#pragma unroll
            for (int hdt = 0; hdt < 4; ++hdt) {
                int vr = nb * 64 + j * 16 + (lane & 7) + (((lane >> 3) & 1) << 3);
                int ch = hdt * 2 + (lane >> 4);
                uint32_t off = (uint32_t)(vr * 128 + ((ch ^ (vr & 7)) << 4));
                ldsm_x4_t(vbh[hdt], sb + AVH + off);
            }
#pragma unroll
            for (int mt = 0; mt < 2; ++mt)
#pragma unroll
                for (int hdt = 0; hdt < 4; ++hdt)
#pragma unroll
                    for (int hf = 0; hf < 2; ++hf)
                        mma16816(yacc[mt][hdt * 2 + hf], pah[mt], vbh[hdt][2 * hf], vbh[hdt][2 * hf + 1]);
#pragma unroll
            for (int mt = 0; mt < 2; ++mt)
#pragma unroll
                for (int hdt = 0; hdt < 4; ++hdt)
#pragma unroll
                    for (int hf = 0; hf < 2; ++hf)
                        mma16816(yacc[mt][hdt * 2 + hf], pal[mt], vbh[hdt][2 * hf], vbh[hdt][2 * hf + 1]);
        }
    }

    // ---- row-sum reduce within quads, normalize, residual add, store ----
#pragma unroll
    for (int mt = 0; mt < 2; ++mt)
#pragma unroll
        for (int i = 0; i < 2; ++i) {
            rs[mt][i] += __shfl_xor_sync(0xffffffffu, rs[mt][i], 1);
            rs[mt][i] += __shfl_xor_sync(0xffffffffu, rs[mt][i], 2);
        }

    int qr = lane >> 2, qc = (lane & 3) * 2;
    int bb = bi / NJ, n = bi % NJ;
#pragma unroll
    for (int mt = 0; mt < 2; ++mt) {
        float inv0 = 1.0f / rs[mt][0];
        float inv1 = 1.0f / rs[mt][1];
        int t0 = wid * 32 + mt * 16 + qr;
#pragma unroll
        for (int nt = 0; nt < 8; ++nt) {
            int hd = nt * 8 + qc;
            float* cc = yacc[mt][nt];
            size_t a0 = ((size_t)(bb * T + t0) * NJ + n) * C + h * HD + hd;
            size_t a1 = ((size_t)(bb * T + t0 + 8) * NJ + n) * C + h * HD + hd;
            float2 x0 = *(const float2*)(x + a0);
            float2 x1 = *(const float2*)(x + a1);
            *(float2*)(out + a0) = make_float2(x0.x + cc[0] * inv0, x0.y + cc[1] * inv0);
            *(float2*)(out + a1) = make_float2(x1.x + cc[2] * inv1, x1.y + cc[3] * inv1);
        }
    }
}

// ---------------- launch ----------------
extern "C" void kernel_launch(void* const* d_in, const int* in_sizes, int n_in,
                              void* d_out, int out_size) {
    const float* x     = (const float*)d_in[0];
    const float* cx    = (const float*)d_in[1];
    const float* gamma = (const float*)d_in[2];
    const float* beta  = (const float*)d_in[3];
    const float* Wq    = (const float*)d_in[4];
    const float* Wk    = (const float*)d_in[5];
    const float* Wv    = (const float*)d_in[6];
    float* out = (float*)d_out;

    cudaFuncSetAttribute(qkv_gemm_mma, cudaFuncAttributeMaxDynamicSharedMemorySize, 4 * QSTG);
    cudaFuncSetAttribute(attn_mma, cudaFuncAttributeMaxDynamicSharedMemorySize, ATT_SMEM);

    ln_pack_kernel<<<2 * RTOT / 8, 256>>>(x, cx, gamma, beta);
    pack_w_kernel<<<3 * C * C / 1024, 256>>>(Wq, Wk, Wv);

    dim3 gg(C / 128, RTOT / 128, 3);
    qkv_gemm_mma<<<gg, 256, 4 * QSTG>>>();

    attn_mma<<<BATCH * H, 256, ATT_SMEM>>>(x, out);
}

// round 12
// speedup vs baseline: 4.8237x; 1.0849x over previous
#include <cuda_runtime.h>
#include <cuda_fp16.h>
#include <cstdint>

#define Bb    16
#define T     256
#define NJ    24
#define C     512
#define H     8
#define HD    64
#define BATCH (Bb*NJ)     // 384
#define RTOT  (BATCH*T)   // 98304

// ---------------- scratch (static device memory; no allocations) ----------------
__device__ uint4 g_xh4[(size_t)RTOT * C / 8];
__device__ uint4 g_xl4[(size_t)RTOT * C / 8];
__device__ uint4 g_ch4[(size_t)RTOT * C / 8];
__device__ uint4 g_cl4[(size_t)RTOT * C / 8];
__device__ uint4 g_wh4[(size_t)3 * C * C / 8];      // W hi only
__device__ uint4 g_qh4[(size_t)RTOT * C / 8];
__device__ uint4 g_ql4[(size_t)RTOT * C / 8];
__device__ uint4 g_kh4[(size_t)RTOT * C / 8];       // k hi only
__device__ uint4 g_vh4[(size_t)RTOT * C / 8];       // v hi only

// ---------------- helpers ----------------
__device__ __forceinline__ uint32_t smem_u32(const void* p) {
    uint32_t a;
    asm("{ .reg .u64 t; cvta.to.shared.u64 t, %1; cvt.u32.u64 %0, t; }" : "=r"(a) : "l"(p));
    return a;
}
__device__ __forceinline__ void cp16(uint32_t dst, const void* src) {
    asm volatile("cp.async.cg.shared.global [%0], [%1], 16;" :: "r"(dst), "l"(src));
}
#define CP_COMMIT() asm volatile("cp.async.commit_group;" ::: "memory")
#define CP_WAIT2()  asm volatile("cp.async.wait_group 2;" ::: "memory")
#define CP_WAIT0()  asm volatile("cp.async.wait_group 0;" ::: "memory")

__device__ __forceinline__ void ldsm_x4(uint32_t* r, uint32_t addr) {
    asm volatile("ldmatrix.sync.aligned.m8n8.x4.shared.b16 {%0,%1,%2,%3}, [%4];"
                 : "=r"(r[0]), "=r"(r[1]), "=r"(r[2]), "=r"(r[3]) : "r"(addr));
}
__device__ __forceinline__ void ldsm_x4_t(uint32_t* r, uint32_t addr) {
    asm volatile("ldmatrix.sync.aligned.m8n8.x4.trans.shared.b16 {%0,%1,%2,%3}, [%4];"
                 : "=r"(r[0]), "=r"(r[1]), "=r"(r[2]), "=r"(r[3]) : "r"(addr));
}
__device__ __forceinline__ void mma16816(float* c, const uint32_t* a,
                                         uint32_t b0, uint32_t b1) {
    asm volatile("mma.sync.aligned.m16n8k16.row.col.f32.f16.f16.f32 "
                 "{%0,%1,%2,%3}, {%4,%5,%6,%7}, {%8,%9}, {%0,%1,%2,%3};"
                 : "+f"(c[0]), "+f"(c[1]), "+f"(c[2]), "+f"(c[3])
                 : "r"(a[0]), "r"(a[1]), "r"(a[2]), "r"(a[3]), "r"(b0), "r"(b1));
}
__device__ __forceinline__ uint32_t pack_hi_lo(float f0, float f1, uint32_t& lo) {
    __half h0 = __float2half_rn(f0);
    __half h1 = __float2half_rn(f1);
    __half l0 = __float2half_rn(f0 - __half2float(h0));
    __half l1 = __float2half_rn(f1 - __half2float(h1));
    __half2 hp(h0, h1), lp(l0, l1);
    lo = *reinterpret_cast<uint32_t*>(&lp);
    return *reinterpret_cast<uint32_t*>(&hp);
}
__device__ __forceinline__ uint32_t pack_hi(float f0, float f1) {
    __half2 hp(__float2half_rn(f0), __float2half_rn(f1));
    return *reinterpret_cast<uint32_t*>(&hp);
}

// ---------------- kernel 1: LN stats + apply + fp16 hi/lo pack ----------------
__global__ void ln_pack_kernel(const float* __restrict__ x, const float* __restrict__ cx,
                               const float* __restrict__ gamma, const float* __restrict__ beta) {
    int warp = threadIdx.x >> 5, lane = threadIdx.x & 31;
    int row = blockIdx.x * 8 + warp;
    const float* src = (row < RTOT) ? x : cx;
    int r  = (row < RTOT) ? row : row - RTOT;
    int bidx = r >> 8;
    int t    = r & 255;
    int bb = bidx / NJ, n = bidx % NJ;
    const float4* p = (const float4*)(src + ((size_t)(bb * T + t) * NJ + n) * C);
    float4 v[4];
    float s = 0.f, sq = 0.f;
#pragma unroll
    for (int i = 0; i < 4; i++) {
        v[i] = p[lane + 32 * i];
        s  += v[i].x + v[i].y + v[i].z + v[i].w;
        sq += v[i].x * v[i].x + v[i].y * v[i].y + v[i].z * v[i].z + v[i].w * v[i].w;
    }
#pragma unroll
    for (int o = 16; o; o >>= 1) {
        s  += __shfl_xor_sync(0xffffffffu, s, o);
        sq += __shfl_xor_sync(0xffffffffu, sq, o);
    }
    float mu = s * (1.0f / C);
    float rs = rsqrtf(sq * (1.0f / C) - mu * mu + 1e-5f);

    __half* dh = (row < RTOT) ? (__half*)g_xh4 : (__half*)g_ch4;
    __half* dl = (row < RTOT) ? (__half*)g_xl4 : (__half*)g_cl4;
    size_t rb = (size_t)r * C;
#pragma unroll
    for (int i = 0; i < 4; i++) {
        int e = (lane + 32 * i) * 4;
        float4 g  = *(const float4*)(gamma + e);
        float4 be = *(const float4*)(beta + e);
        float f0 = (v[i].x - mu) * rs * g.x + be.x;
        float f1 = (v[i].y - mu) * rs * g.y + be.y;
        float f2 = (v[i].z - mu) * rs * g.z + be.z;
        float f3 = (v[i].w - mu) * rs * g.w + be.w;
        uint32_t lo0, lo1;
        uint32_t hi0 = pack_hi_lo(f0, f1, lo0);
        uint32_t hi1 = pack_hi_lo(f2, f3, lo1);
        *(uint2*)(dh + rb + e) = make_uint2(hi0, hi1);
        *(uint2*)(dl + rb + e) = make_uint2(lo0, lo1);
    }
}

// ---------------- kernel 2: pack weights fp16 hi ----------------
__global__ void pack_w_kernel(const float* __restrict__ Wq, const float* __restrict__ Wk,
                              const float* __restrict__ Wv) {
    size_t e = ((size_t)blockIdx.x * 256 + threadIdx.x) * 4;
    int z = (int)(e / ((size_t)C * C));
    size_t rem = e % ((size_t)C * C);
    const float* W = (z == 0) ? Wq : (z == 1) ? Wk : Wv;
    float4 w = *(const float4*)(W + rem);
    *(uint2*)((__half*)g_wh4 + e) = make_uint2(pack_hi(w.x, w.y), pack_hi(w.z, w.w));
}

// ---------------- kernel 3: QKV GEMM, fp16 2-product, BM=64/BN=128/BK=32 ----
// 2 CTAs/SM. stage = 16KB: Ah[4K] Al[4K] Bh[8K]; 4 stages = 64KB.
// rows 64B (4 x 16B chunks), swizzle chunk ^ ((row>>1)&3).
#define QSTG 16384

__device__ __forceinline__ void qfill(uint32_t s, int k0,
    const __half* Ah_g, const __half* Al_g, const __half* Bh_g,
    int r0, int o0, int tid) {
    {   // A: 64 rows x 4 chunks = 256, one per thread
        int row = tid >> 2, c = tid & 3;
        uint32_t doff = (uint32_t)(row * 64 + ((c ^ ((row >> 1) & 3)) << 4));
        size_t ga = (size_t)(r0 + row) * C + k0 + c * 8;
        cp16(s + doff,        Ah_g + ga);
        cp16(s + 4096 + doff, Al_g + ga);
    }
#pragma unroll
    for (int j = 0; j < 2; ++j) {   // B: 128 rows x 4 chunks = 512, two per thread
        int idx = j * 256 + tid;
        int row = idx >> 2, c = idx & 3;
        uint32_t doff = (uint32_t)(row * 64 + ((c ^ ((row >> 1) & 3)) << 4));
        size_t gb = (size_t)(o0 + row) * C + k0 + c * 8;
        cp16(s + 8192 + doff, Bh_g + gb);
    }
}

__global__ __launch_bounds__(256, 2) void qkv_gemm_mma() {
    extern __shared__ char sm[];
    uint32_t sb = smem_u32(sm);
    int tid = threadIdx.x;
    int wid = tid >> 5, lane = tid & 31;
    int wm = wid & 1, wn = wid >> 1;          // 2(M) x 4(N) warps, warp tile 32x32

    int z = blockIdx.z;
    const __half* Ah_g = (z == 0) ? (const __half*)g_xh4 : (const __half*)g_ch4;
    const __half* Al_g = (z == 0) ? (const __half*)g_xl4 : (const __half*)g_cl4;
    const __half* Bh_g = (const __half*)g_wh4 + (size_t)z * C * C;

    int r0 = blockIdx.y * 64;
    int o0 = blockIdx.x * 128;

    float acc[2][4][4];
#pragma unroll
    for (int i = 0; i < 2; i++)
#pragma unroll
        for (int j = 0; j < 4; j++)
#pragma unroll
            for (int q = 0; q < 4; q++) acc[i][j][q] = 0.f;

    int a_row   = wm * 32 + (lane & 15);
    int a_khalf = lane >> 4;
    int b_nrow  = wn * 32 + (lane & 7) + ((lane >> 4) << 3);
    int b_khalf = (lane >> 3) & 1;

    qfill(sb,            0,  Ah_g, Al_g, Bh_g, r0, o0, tid); CP_COMMIT();
    qfill(sb + QSTG,     32, Ah_g, Al_g, Bh_g, r0, o0, tid); CP_COMMIT();
    qfill(sb + 2 * QSTG, 64, Ah_g, Al_g, Bh_g, r0, o0, tid); CP_COMMIT();

    for (int c = 0; c < 16; ++c) {       // 16 chunks of BK=32
        CP_WAIT2();
        __syncthreads();
        if (c + 3 < 16) {
            qfill(sb + ((c + 3) & 3) * QSTG, (c + 3) * 32, Ah_g, Al_g, Bh_g, r0, o0, tid);
        }
        CP_COMMIT();

        uint32_t base = sb + (c & 3) * QSTG;
#pragma unroll
        for (int ks = 0; ks < 2; ++ks) {
            uint32_t ah[2][4], al[2][4];
#pragma unroll
            for (int mt = 0; mt < 2; ++mt) {
                int row = a_row + mt * 16;
                int ch = ks * 2 + a_khalf;
                uint32_t off = (uint32_t)(row * 64 + ((ch ^ ((row >> 1) & 3)) << 4));
                ldsm_x4(ah[mt], base + off);
                ldsm_x4(al[mt], base + 4096 + off);
            }
            uint32_t bh[2][4];
#pragma unroll
            for (int ng = 0; ng < 2; ++ng) {
                int nr = b_nrow + ng * 16;
                int ch = ks * 2 + b_khalf;
                uint32_t off = (uint32_t)(nr * 64 + ((ch ^ ((nr >> 1) & 3)) << 4));
                ldsm_x4(bh[ng], base + 8192 + off);
            }
            // product-major sweeps: 8 distinct accumulators per sweep
#pragma unroll
            for (int mt = 0; mt < 2; ++mt)
#pragma unroll
                for (int ng = 0; ng < 2; ++ng)
#pragma unroll
                    for (int hf = 0; hf < 2; ++hf)
                        mma16816(acc[mt][ng * 2 + hf], ah[mt], bh[ng][2 * hf], bh[ng][2 * hf + 1]);
#pragma unroll
            for (int mt = 0; mt < 2; ++mt)
#pragma unroll
                for (int ng = 0; ng < 2; ++ng)
#pragma unroll
                    for (int hf = 0; hf < 2; ++hf)
                        mma16816(acc[mt][ng * 2 + hf], al[mt], bh[ng][2 * hf], bh[ng][2 * hf + 1]);
        }
        __syncthreads();
    }

    // ---- epilogue: q -> hi+lo; k,v -> hi only ----
    int qr = lane >> 2, qc = (lane & 3) * 2;
#pragma unroll
    for (int mt = 0; mt < 2; ++mt) {
        int row = r0 + wm * 32 + mt * 16 + qr;
#pragma unroll
        for (int nt = 0; nt < 4; ++nt) {
            int col = o0 + wn * 32 + nt * 8 + qc;
            float* cc = acc[mt][nt];
            if (z == 0) {
                uint32_t l0, l1;
                uint32_t h0 = pack_hi_lo(cc[0], cc[1], l0);
                uint32_t h1 = pack_hi_lo(cc[2], cc[3], l1);
                __half* dh = (__half*)g_qh4;
                __half* dl = (__half*)g_ql4;
                *(uint32_t*)(dh + (size_t)row * C + col)       = h0;
                *(uint32_t*)(dl + (size_t)row * C + col)       = l0;
                *(uint32_t*)(dh + (size_t)(row + 8) * C + col) = h1;
                *(uint32_t*)(dl + (size_t)(row + 8) * C + col) = l1;
            } else {
                __half* dh = (z == 1) ? (__half*)g_kh4 : (__half*)g_vh4;
                *(uint32_t*)(dh + (size_t)row * C + col)       = pack_hi(cc[0], cc[1]);
                *(uint32_t*)(dh + (size_t)(row + 8) * C + col) = pack_hi(cc[2], cc[3]);
            }
        }
    }
}

// ---------------- kernel 4: attention via mma.sync (fp16 2-product) ----------------
// block = (bi, h); 8 warps; warp w owns query rows [32w, 32w+32).
// smem: QH[32K] QL[32K] KH[32K] VH[32K] = 128KB.
#define AQH 0
#define AQL 32768
#define AKH 65536
#define AVH 98304
#define ATT_SMEM 131072

__global__ __launch_bounds__(256, 1) void attn_mma(const float* __restrict__ x,
                                                   float* __restrict__ out) {
    extern __shared__ char sm[];
    uint32_t sb = smem_u32(sm);
    int tid = threadIdx.x;
    int wid = tid >> 5, lane = tid & 31;

    int bi = blockIdx.x / H;
    int h  = blockIdx.x % H;
    size_t rbase = (size_t)bi * T;

    const __half* qh_g = (const __half*)g_qh4;
    const __half* ql_g = (const __half*)g_ql4;
    const __half* kh_g = (const __half*)g_kh4;
    const __half* vh_g = (const __half*)g_vh4;

    for (int i = tid; i < 2048; i += 256) {
        int r = i >> 3, c = i & 7;
        uint32_t off = (uint32_t)(r * 128 + ((c ^ (r & 7)) << 4));
        size_t ga = (rbase + r) * C + h * HD + c * 8;
        cp16(sb + AKH + off, kh_g + ga);
        cp16(sb + AVH + off, vh_g + ga);
    }
    for (int i = lane; i < 256; i += 32) {
        int r = i >> 3, c = i & 7;
        uint32_t off = (uint32_t)(wid * 4096 + r * 128 + ((c ^ (r & 7)) << 4));
        size_t ga = (rbase + wid * 32 + r) * C + h * HD + c * 8;
        cp16(sb + AQH + off, qh_g + ga);
        cp16(sb + AQL + off, ql_g + ga);
    }
    CP_COMMIT();
    CP_WAIT0();
    __syncthreads();

    float yacc[2][8][4];
#pragma unroll
    for (int i = 0; i < 2; i++)
#pragma unroll
        for (int j = 0; j < 8; j++)
#pragma unroll
            for (int q = 0; q < 4; q++) yacc[i][j][q] = 0.f;
    float rs[2][2] = {{0.f, 0.f}, {0.f, 0.f}};

    uint32_t qbase = sb + (uint32_t)(wid * 4096);

    for (int nb = 0; nb < 4; ++nb) {
        float sacc[2][8][4];
#pragma unroll
        for (int i = 0; i < 2; i++)
#pragma unroll
            for (int j = 0; j < 8; j++)
#pragma unroll
                for (int q = 0; q < 4; q++) sacc[i][j][q] = 0.f;

#pragma unroll
        for (int kt = 0; kt < 4; ++kt) {
            uint32_t ah[2][4], al[2][4];
#pragma unroll
            for (int mt = 0; mt < 2; ++mt) {
                int row = mt * 16 + (lane & 15);
                int ch = kt * 2 + (lane >> 4);
                uint32_t off = (uint32_t)(row * 128 + ((ch ^ (row & 7)) << 4));
                ldsm_x4(ah[mt], qbase + AQH + off);
                ldsm_x4(al[mt], qbase + AQL + off);
            }
            uint32_t kbh[4][4];
#pragma unroll
            for (int ng = 0; ng < 4; ++ng) {
                int nr = nb * 64 + ng * 16 + (lane & 7) + ((lane >> 4) << 3);
                int ch = kt * 2 + ((lane >> 3) & 1);
                uint32_t off = (uint32_t)(nr * 128 + ((ch ^ (nr & 7)) << 4));
                ldsm_x4(kbh[ng], sb + AKH + off);
            }
#pragma unroll
            for (int mt = 0; mt < 2; ++mt)
#pragma unroll
                for (int ng = 0; ng < 4; ++ng)
#pragma unroll
                    for (int hf = 0; hf < 2; ++hf)
                        mma16816(sacc[mt][ng * 2 + hf], ah[mt], kbh[ng][2 * hf], kbh[ng][2 * hf + 1]);
#pragma unroll
            for (int mt = 0; mt < 2; ++mt)
#pragma unroll
                for (int ng = 0; ng < 4; ++ng)
#pragma unroll
                    for (int hf = 0; hf < 2; ++hf)
                        mma16816(sacc[mt][ng * 2 + hf], al[mt], kbh[ng][2 * hf], kbh[ng][2 * hf + 1]);
        }

#pragma unroll
        for (int mt = 0; mt < 2; ++mt)
#pragma unroll
            for (int nt = 0; nt < 8; ++nt) {
                float* cc = sacc[mt][nt];
                cc[0] = __expf(cc[0] * 0.125f);
                cc[1] = __expf(cc[1] * 0.125f);
                cc[2] = __expf(cc[2] * 0.125f);
                cc[3] = __expf(cc[3] * 0.125f);
                rs[mt][0] += cc[0] + cc[1];
                rs[mt][1] += cc[2] + cc[3];
            }

#pragma unroll
        for (int j = 0; j < 4; ++j) {
            uint32_t pah[2][4], pal[2][4];
#pragma unroll
            for (int mt = 0; mt < 2; ++mt) {
                pah[mt][0] = pack_hi_lo(sacc[mt][2 * j][0],     sacc[mt][2 * j][1],     pal[mt][0]);
                pah[mt][1] = pack_hi_lo(sacc[mt][2 * j][2],     sacc[mt][2 * j][3],     pal[mt][1]);
                pah[mt][2] = pack_hi_lo(sacc[mt][2 * j + 1][0], sacc[mt][2 * j + 1][1], pal[mt][2]);
                pah[mt][3] = pack_hi_lo(sacc[mt][2 * j + 1][2], sacc[mt][2 * j + 1][3], pal[mt][3]);
            }
            uint32_t vbh[4][4];
#pragma unroll
            for (int hdt = 0; hdt < 4; ++hdt) {
                int vr = nb * 64 + j * 16 + (lane & 7) + (((lane >> 3) & 1) << 3);
                int ch = hdt * 2 + (lane >> 4);
                uint32_t off = (uint32_t)(vr * 128 + ((ch ^ (vr & 7)) << 4));
                ldsm_x4_t(vbh[hdt], sb + AVH + off);
            }
#pragma unroll
            for (int mt = 0; mt < 2; ++mt)
#pragma unroll
                for (int hdt = 0; hdt < 4; ++hdt)
#pragma unroll
                    for (int hf = 0; hf < 2; ++hf)
                        mma16816(yacc[mt][hdt * 2 + hf], pah[mt], vbh[hdt][2 * hf], vbh[hdt][2 * hf + 1]);
#pragma unroll
            for (int mt = 0; mt < 2; ++mt)
#pragma unroll
                for (int hdt = 0; hdt < 4; ++hdt)
#pragma unroll
                    for (int hf = 0; hf < 2; ++hf)
                        mma16816(yacc[mt][hdt * 2 + hf], pal[mt], vbh[hdt][2 * hf], vbh[hdt][2 * hf + 1]);
        }
    }

#pragma unroll
    for (int mt = 0; mt < 2; ++mt)
#pragma unroll
        for (int i = 0; i < 2; ++i) {
            rs[mt][i] += __shfl_xor_sync(0xffffffffu, rs[mt][i], 1);
            rs[mt][i] += __shfl_xor_sync(0xffffffffu, rs[mt][i], 2);
        }

    int qr = lane >> 2, qc = (lane & 3) * 2;
    int bb = bi / NJ, n = bi % NJ;
#pragma unroll
    for (int mt = 0; mt < 2; ++mt) {
        float inv0 = 1.0f / rs[mt][0];
        float inv1 = 1.0f / rs[mt][1];
        int t0 = wid * 32 + mt * 16 + qr;
#pragma unroll
        for (int nt = 0; nt < 8; ++nt) {
            int hd = nt * 8 + qc;
            float* cc = yacc[mt][nt];
            size_t a0 = ((size_t)(bb * T + t0) * NJ + n) * C + h * HD + hd;
            size_t a1 = ((size_t)(bb * T + t0 + 8) * NJ + n) * C + h * HD + hd;
            float2 x0 = *(const float2*)(x + a0);
            float2 x1 = *(const float2*)(x + a1);
            *(float2*)(out + a0) = make_float2(x0.x + cc[0] * inv0, x0.y + cc[1] * inv0);
            *(float2*)(out + a1) = make_float2(x1.x + cc[2] * inv1, x1.y + cc[3] * inv1);
        }
    }
}

// ---------------- launch ----------------
extern "C" void kernel_launch(void* const* d_in, const int* in_sizes, int n_in,
                              void* d_out, int out_size) {
    const float* x     = (const float*)d_in[0];
    const float* cx    = (const float*)d_in[1];
    const float* gamma = (const float*)d_in[2];
    const float* beta  = (const float*)d_in[3];
    const float* Wq    = (const float*)d_in[4];
    const float* Wk    = (const float*)d_in[5];
    const float* Wv    = (const float*)d_in[6];
    float* out = (float*)d_out;

    cudaFuncSetAttribute(qkv_gemm_mma, cudaFuncAttributeMaxDynamicSharedMemorySize, 4 * QSTG);
    cudaFuncSetAttribute(attn_mma, cudaFuncAttributeMaxDynamicSharedMemorySize, ATT_SMEM);

    ln_pack_kernel<<<2 * RTOT / 8, 256>>>(x, cx, gamma, beta);
    pack_w_kernel<<<3 * C * C / 1024, 256>>>(Wq, Wk, Wv);

    dim3 gg(C / 128, RTOT / 64, 3);
    qkv_gemm_mma<<<gg, 256, 4 * QSTG>>>();

    attn_mma<<<BATCH * H, 256, ATT_SMEM>>>(x, out);
}

// round 13
// speedup vs baseline: 7.7937x; 1.6157x over previous
#include <cuda_runtime.h>
#include <cuda_fp16.h>
#include <cstdint>

#define Bb    16
#define T     256
#define NJ    24
#define C     512
#define H     8
#define HD    64
#define BATCH (Bb*NJ)     // 384
#define RTOT  (BATCH*T)   // 98304

// ---------------- scratch (static device memory; no allocations) ----------------
__device__ uint4 g_xh4[(size_t)RTOT * C / 8];       // LN(x) fp16
__device__ uint4 g_ch4[(size_t)RTOT * C / 8];       // LN(cx) fp16
__device__ uint4 g_wh4[(size_t)3 * C * C / 8];      // W fp16
__device__ uint4 g_qh4[(size_t)RTOT * C / 8];       // q fp16
__device__ uint4 g_kh4[(size_t)RTOT * C / 8];       // k fp16
__device__ uint4 g_vh4[(size_t)RTOT * C / 8];       // v fp16

// ---------------- helpers ----------------
__device__ __forceinline__ uint32_t smem_u32(const void* p) {
    uint32_t a;
    asm("{ .reg .u64 t; cvta.to.shared.u64 t, %1; cvt.u32.u64 %0, t; }" : "=r"(a) : "l"(p));
    return a;
}
__device__ __forceinline__ void cp16(uint32_t dst, const void* src) {
    asm volatile("cp.async.cg.shared.global [%0], [%1], 16;" :: "r"(dst), "l"(src));
}
#define CP_COMMIT() asm volatile("cp.async.commit_group;" ::: "memory")
#define CP_WAIT2()  asm volatile("cp.async.wait_group 2;" ::: "memory")
#define CP_WAIT0()  asm volatile("cp.async.wait_group 0;" ::: "memory")

__device__ __forceinline__ void ldsm_x4(uint32_t* r, uint32_t addr) {
    asm volatile("ldmatrix.sync.aligned.m8n8.x4.shared.b16 {%0,%1,%2,%3}, [%4];"
                 : "=r"(r[0]), "=r"(r[1]), "=r"(r[2]), "=r"(r[3]) : "r"(addr));
}
__device__ __forceinline__ void ldsm_x4_t(uint32_t* r, uint32_t addr) {
    asm volatile("ldmatrix.sync.aligned.m8n8.x4.trans.shared.b16 {%0,%1,%2,%3}, [%4];"
                 : "=r"(r[0]), "=r"(r[1]), "=r"(r[2]), "=r"(r[3]) : "r"(addr));
}
__device__ __forceinline__ void mma16816(float* c, const uint32_t* a,
                                         uint32_t b0, uint32_t b1) {
    asm volatile("mma.sync.aligned.m16n8k16.row.col.f32.f16.f16.f32 "
                 "{%0,%1,%2,%3}, {%4,%5,%6,%7}, {%8,%9}, {%0,%1,%2,%3};"
                 : "+f"(c[0]), "+f"(c[1]), "+f"(c[2]), "+f"(c[3])
                 : "r"(a[0]), "r"(a[1]), "r"(a[2]), "r"(a[3]), "r"(b0), "r"(b1));
}
__device__ __forceinline__ uint32_t pack_hi(float f0, float f1) {
    __half2 hp(__float2half_rn(f0), __float2half_rn(f1));
    return *reinterpret_cast<uint32_t*>(&hp);
}

// ---------------- kernel 1: LN stats + apply + fp16 pack ----------------
__global__ void ln_pack_kernel(const float* __restrict__ x, const float* __restrict__ cx,
                               const float* __restrict__ gamma, const float* __restrict__ beta) {
    int warp = threadIdx.x >> 5, lane = threadIdx.x & 31;
    int row = blockIdx.x * 8 + warp;
    const float* src = (row < RTOT) ? x : cx;
    int r  = (row < RTOT) ? row : row - RTOT;
    int bidx = r >> 8;
    int t    = r & 255;
    int bb = bidx / NJ, n = bidx % NJ;
    const float4* p = (const float4*)(src + ((size_t)(bb * T + t) * NJ + n) * C);
    float4 v[4];
    float s = 0.f, sq = 0.f;
#pragma unroll
    for (int i = 0; i < 4; i++) {
        v[i] = p[lane + 32 * i];
        s  += v[i].x + v[i].y + v[i].z + v[i].w;
        sq += v[i].x * v[i].x + v[i].y * v[i].y + v[i].z * v[i].z + v[i].w * v[i].w;
    }
#pragma unroll
    for (int o = 16; o; o >>= 1) {
        s  += __shfl_xor_sync(0xffffffffu, s, o);
        sq += __shfl_xor_sync(0xffffffffu, sq, o);
    }
    float mu = s * (1.0f / C);
    float rs = rsqrtf(sq * (1.0f / C) - mu * mu + 1e-5f);

    __half* dh = (row < RTOT) ? (__half*)g_xh4 : (__half*)g_ch4;
    size_t rb = (size_t)r * C;
#pragma unroll
    for (int i = 0; i < 4; i++) {
        int e = (lane + 32 * i) * 4;
        float4 g  = *(const float4*)(gamma + e);
        float4 be = *(const float4*)(beta + e);
        float f0 = (v[i].x - mu) * rs * g.x + be.x;
        float f1 = (v[i].y - mu) * rs * g.y + be.y;
        float f2 = (v[i].z - mu) * rs * g.z + be.z;
        float f3 = (v[i].w - mu) * rs * g.w + be.w;
        *(uint2*)(dh + rb + e) = make_uint2(pack_hi(f0, f1), pack_hi(f2, f3));
    }
}

// ---------------- kernel 2: pack weights fp16 ----------------
__global__ void pack_w_kernel(const float* __restrict__ Wq, const float* __restrict__ Wk,
                              const float* __restrict__ Wv) {
    size_t e = ((size_t)blockIdx.x * 256 + threadIdx.x) * 4;
    int z = (int)(e / ((size_t)C * C));
    size_t rem = e % ((size_t)C * C);
    const float* W = (z == 0) ? Wq : (z == 1) ? Wk : Wv;
    float4 w = *(const float4*)(W + rem);
    *(uint2*)((__half*)g_wh4 + e) = make_uint2(pack_hi(w.x, w.y), pack_hi(w.z, w.w));
}

// ---------------- kernel 3: QKV GEMM, fp16 single-product, BM=64/BN=128/BK=32 ----
// 2 CTAs/SM. stage = 12KB: Ah[4K] Bh[8K]; 4 stages = 48KB.
// rows 64B (4 x 16B chunks), swizzle chunk ^ ((row>>1)&3).
#define QSTG 12288

__device__ __forceinline__ void qfill(uint32_t s, int k0,
    const __half* Ah_g, const __half* Bh_g, int r0, int o0, int tid) {
    {   // A: 64 rows x 4 chunks = 256, one per thread
        int row = tid >> 2, c = tid & 3;
        uint32_t doff = (uint32_t)(row * 64 + ((c ^ ((row >> 1) & 3)) << 4));
        size_t ga = (size_t)(r0 + row) * C + k0 + c * 8;
        cp16(s + doff, Ah_g + ga);
    }
#pragma unroll
    for (int j = 0; j < 2; ++j) {   // B: 128 rows x 4 chunks = 512, two per thread
        int idx = j * 256 + tid;
        int row = idx >> 2, c = idx & 3;
        uint32_t doff = (uint32_t)(row * 64 + ((c ^ ((row >> 1) & 3)) << 4));
        size_t gb = (size_t)(o0 + row) * C + k0 + c * 8;
        cp16(s + 4096 + doff, Bh_g + gb);
    }
}

__global__ __launch_bounds__(256, 2) void qkv_gemm_mma() {
    extern __shared__ char sm[];
    uint32_t sb = smem_u32(sm);
    int tid = threadIdx.x;
    int wid = tid >> 5, lane = tid & 31;
    int wm = wid & 1, wn = wid >> 1;          // 2(M) x 4(N) warps, warp tile 32x32

    int z = blockIdx.z;
    const __half* Ah_g = (z == 0) ? (const __half*)g_xh4 : (const __half*)g_ch4;
    const __half* Bh_g = (const __half*)g_wh4 + (size_t)z * C * C;
    __half* dst = (z == 0) ? (__half*)g_qh4 : (z == 1) ? (__half*)g_kh4 : (__half*)g_vh4;

    int r0 = blockIdx.y * 64;
    int o0 = blockIdx.x * 128;

    float acc[2][4][4];
#pragma unroll
    for (int i = 0; i < 2; i++)
#pragma unroll
        for (int j = 0; j < 4; j++)
#pragma unroll
            for (int q = 0; q < 4; q++) acc[i][j][q] = 0.f;

    int a_row   = wm * 32 + (lane & 15);
    int a_khalf = lane >> 4;
    int b_nrow  = wn * 32 + (lane & 7) + ((lane >> 4) << 3);
    int b_khalf = (lane >> 3) & 1;

    qfill(sb,            0,  Ah_g, Bh_g, r0, o0, tid); CP_COMMIT();
    qfill(sb + QSTG,     32, Ah_g, Bh_g, r0, o0, tid); CP_COMMIT();
    qfill(sb + 2 * QSTG, 64, Ah_g, Bh_g, r0, o0, tid); CP_COMMIT();

    for (int c = 0; c < 16; ++c) {       // 16 chunks of BK=32
        CP_WAIT2();
        __syncthreads();
        if (c + 3 < 16) {
            qfill(sb + ((c + 3) & 3) * QSTG, (c + 3) * 32, Ah_g, Bh_g, r0, o0, tid);
        }
        CP_COMMIT();

        uint32_t base = sb + (c & 3) * QSTG;
#pragma unroll
        for (int ks = 0; ks < 2; ++ks) {
            uint32_t ah[2][4];
#pragma unroll
            for (int mt = 0; mt < 2; ++mt) {
                int row = a_row + mt * 16;
                int ch = ks * 2 + a_khalf;
                uint32_t off = (uint32_t)(row * 64 + ((ch ^ ((row >> 1) & 3)) << 4));
                ldsm_x4(ah[mt], base + off);
            }
            uint32_t bh[2][4];
#pragma unroll
            for (int ng = 0; ng < 2; ++ng) {
                int nr = b_nrow + ng * 16;
                int ch = ks * 2 + b_khalf;
                uint32_t off = (uint32_t)(nr * 64 + ((ch ^ ((nr >> 1) & 3)) << 4));
                ldsm_x4(bh[ng], base + 4096 + off);
            }
#pragma unroll
            for (int mt = 0; mt < 2; ++mt)
#pragma unroll
                for (int ng = 0; ng < 2; ++ng)
#pragma unroll
                    for (int hf = 0; hf < 2; ++hf)
                        mma16816(acc[mt][ng * 2 + hf], ah[mt], bh[ng][2 * hf], bh[ng][2 * hf + 1]);
        }
        __syncthreads();
    }

    // ---- epilogue: fp16 store ----
    int qr = lane >> 2, qc = (lane & 3) * 2;
#pragma unroll
    for (int mt = 0; mt < 2; ++mt) {
        int row = r0 + wm * 32 + mt * 16 + qr;
#pragma unroll
        for (int nt = 0; nt < 4; ++nt) {
            int col = o0 + wn * 32 + nt * 8 + qc;
            float* cc = acc[mt][nt];
            *(uint32_t*)(dst + (size_t)row * C + col)       = pack_hi(cc[0], cc[1]);
            *(uint32_t*)(dst + (size_t)(row + 8) * C + col) = pack_hi(cc[2], cc[3]);
        }
    }
}

// ---------------- kernel 4: attention via mma.sync (fp16 single-product) ----------------
// block = (bi, h); 8 warps; warp w owns query rows [32w, 32w+32).
// smem: QH[32K] KH[32K] VH[32K] = 96KB. rows 128B, 8x16B chunks, swizzle chunk^(row&7).
#define AQH 0
#define AKH 32768
#define AVH 65536
#define ATT_SMEM 98304

__global__ __launch_bounds__(256, 1) void attn_mma(const float* __restrict__ x,
                                                   float* __restrict__ out) {
    extern __shared__ char sm[];
    uint32_t sb = smem_u32(sm);
    int tid = threadIdx.x;
    int wid = tid >> 5, lane = tid & 31;

    int bi = blockIdx.x / H;
    int h  = blockIdx.x % H;
    size_t rbase = (size_t)bi * T;

    const __half* qh_g = (const __half*)g_qh4;
    const __half* kh_g = (const __half*)g_kh4;
    const __half* vh_g = (const __half*)g_vh4;

    for (int i = tid; i < 2048; i += 256) {
        int r = i >> 3, c = i & 7;
        uint32_t off = (uint32_t)(r * 128 + ((c ^ (r & 7)) << 4));
        size_t ga = (rbase + r) * C + h * HD + c * 8;
        cp16(sb + AKH + off, kh_g + ga);
        cp16(sb + AVH + off, vh_g + ga);
    }
    for (int i = lane; i < 256; i += 32) {
        int r = i >> 3, c = i & 7;
        uint32_t off = (uint32_t)(wid * 4096 + r * 128 + ((c ^ (r & 7)) << 4));
        size_t ga = (rbase + wid * 32 + r) * C + h * HD + c * 8;
        cp16(sb + AQH + off, qh_g + ga);
    }
    CP_COMMIT();
    CP_WAIT0();
    __syncthreads();

    float yacc[2][8][4];
#pragma unroll
    for (int i = 0; i < 2; i++)
#pragma unroll
        for (int j = 0; j < 8; j++)
#pragma unroll
            for (int q = 0; q < 4; q++) yacc[i][j][q] = 0.f;
    float rs[2][2] = {{0.f, 0.f}, {0.f, 0.f}};

    uint32_t qbase = sb + (uint32_t)(wid * 4096);

    for (int nb = 0; nb < 4; ++nb) {         // key blocks of 64
        float sacc[2][8][4];
#pragma unroll
        for (int i = 0; i < 2; i++)
#pragma unroll
            for (int j = 0; j < 8; j++)
#pragma unroll
                for (int q = 0; q < 4; q++) sacc[i][j][q] = 0.f;

        // ---- S = Qh Kh^T over hd (4 k16 steps) ----
#pragma unroll
        for (int kt = 0; kt < 4; ++kt) {
            uint32_t ah[2][4];
#pragma unroll
            for (int mt = 0; mt < 2; ++mt) {
                int row = mt * 16 + (lane & 15);
                int ch = kt * 2 + (lane >> 4);
                uint32_t off = (uint32_t)(row * 128 + ((ch ^ (row & 7)) << 4));
                ldsm_x4(ah[mt], qbase + AQH + off);
            }
            uint32_t kbh[4][4];
#pragma unroll
            for (int ng = 0; ng < 4; ++ng) {
                int nr = nb * 64 + ng * 16 + (lane & 7) + ((lane >> 4) << 3);
                int ch = kt * 2 + ((lane >> 3) & 1);
                uint32_t off = (uint32_t)(nr * 128 + ((ch ^ (nr & 7)) << 4));
                ldsm_x4(kbh[ng], sb + AKH + off);
            }
#pragma unroll
            for (int mt = 0; mt < 2; ++mt)
#pragma unroll
                for (int ng = 0; ng < 4; ++ng)
#pragma unroll
                    for (int hf = 0; hf < 2; ++hf)
                        mma16816(sacc[mt][ng * 2 + hf], ah[mt], kbh[ng][2 * hf], kbh[ng][2 * hf + 1]);
        }

        // ---- E = exp(S/8); accumulate row sums ----
#pragma unroll
        for (int mt = 0; mt < 2; ++mt)
#pragma unroll
            for (int nt = 0; nt < 8; ++nt) {
                float* cc = sacc[mt][nt];
                cc[0] = __expf(cc[0] * 0.125f);
                cc[1] = __expf(cc[1] * 0.125f);
                cc[2] = __expf(cc[2] * 0.125f);
                cc[3] = __expf(cc[3] * 0.125f);
                rs[mt][0] += cc[0] + cc[1];
                rs[mt][1] += cc[2] + cc[3];
            }

        // ---- Y += Ph Vh ----
#pragma unroll
        for (int j = 0; j < 4; ++j) {
            uint32_t pah[2][4];
#pragma unroll
            for (int mt = 0; mt < 2; ++mt) {
                pah[mt][0] = pack_hi(sacc[mt][2 * j][0],     sacc[mt][2 * j][1]);
                pah[mt][1] = pack_hi(sacc[mt][2 * j][2],     sacc[mt][2 * j][3]);
                pah[mt][2] = pack_hi(sacc[mt][2 * j + 1][0], sacc[mt][2 * j + 1][1]);
                pah[mt][3] = pack_hi(sacc[mt][2 * j + 1][2], sacc[mt][2 * j + 1][3]);
            }
            uint32_t vbh[4][4];
#pragma unroll
            for (int hdt = 0; hdt < 4; ++hdt) {
                int vr = nb * 64 + j * 16 + (lane & 7) + (((lane >> 3) & 1) << 3);
                int ch = hdt * 2 + (lane >> 4);
                uint32_t off = (uint32_t)(vr * 128 + ((ch ^ (vr & 7)) << 4));
                ldsm_x4_t(vbh[hdt], sb + AVH + off);
            }
#pragma unroll
            for (int mt = 0; mt < 2; ++mt)
#pragma unroll
                for (int hdt = 0; hdt < 4; ++hdt)
#pragma unroll
                    for (int hf = 0; hf < 2; ++hf)
                        mma16816(yacc[mt][hdt * 2 + hf], pah[mt], vbh[hdt][2 * hf], vbh[hdt][2 * hf + 1]);
        }
    }

    // ---- row-sum reduce within quads, normalize, residual add, store ----
#pragma unroll
    for (int mt = 0; mt < 2; ++mt)
#pragma unroll
        for (int i = 0; i < 2; ++i) {
            rs[mt][i] += __shfl_xor_sync(0xffffffffu, rs[mt][i], 1);
            rs[mt][i] += __shfl_xor_sync(0xffffffffu, rs[mt][i], 2);
        }

    int qr = lane >> 2, qc = (lane & 3) * 2;
    int bb = bi / NJ, n = bi % NJ;
#pragma unroll
    for (int mt = 0; mt < 2; ++mt) {
        float inv0 = 1.0f / rs[mt][0];
        float inv1 = 1.0f / rs[mt][1];
        int t0 = wid * 32 + mt * 16 + qr;
#pragma unroll
        for (int nt = 0; nt < 8; ++nt) {
            int hd = nt * 8 + qc;
            float* cc = yacc[mt][nt];
            size_t a0 = ((size_t)(bb * T + t0) * NJ + n) * C + h * HD + hd;
            size_t a1 = ((size_t)(bb * T + t0 + 8) * NJ + n) * C + h * HD + hd;
            float2 x0 = *(const float2*)(x + a0);
            float2 x1 = *(const float2*)(x + a1);
            *(float2*)(out + a0) = make_float2(x0.x + cc[0] * inv0, x0.y + cc[1] * inv0);
            *(float2*)(out + a1) = make_float2(x1.x + cc[2] * inv1, x1.y + cc[3] * inv1);
        }
    }
}

// ---------------- launch ----------------
extern "C" void kernel_launch(void* const* d_in, const int* in_sizes, int n_in,
                              void* d_out, int out_size) {
    const float* x     = (const float*)d_in[0];
    const float* cx    = (const float*)d_in[1];
    const float* gamma = (const float*)d_in[2];
    const float* beta  = (const float*)d_in[3];
    const float* Wq    = (const float*)d_in[4];
    const float* Wk    = (const float*)d_in[5];
    const float* Wv    = (const float*)d_in[6];
    float* out = (float*)d_out;

    cudaFuncSetAttribute(qkv_gemm_mma, cudaFuncAttributeMaxDynamicSharedMemorySize, 4 * QSTG);
    cudaFuncSetAttribute(attn_mma, cudaFuncAttributeMaxDynamicSharedMemorySize, ATT_SMEM);

    ln_pack_kernel<<<2 * RTOT / 8, 256>>>(x, cx, gamma, beta);
    pack_w_kernel<<<3 * C * C / 1024, 256>>>(Wq, Wk, Wv);

    dim3 gg(C / 128, RTOT / 64, 3);
    qkv_gemm_mma<<<gg, 256, 4 * QSTG>>>();

    attn_mma<<<BATCH * H, 256, ATT_SMEM>>>(x, out);
}

// round 14
// speedup vs baseline: 8.4458x; 1.0837x over previous
#include <cuda_runtime.h>
#include <cuda_fp16.h>
#include <cstdint>

#define Bb    16
#define T     256
#define NJ    24
#define C     512
#define H     8
#define HD    64
#define BATCH (Bb*NJ)     // 384
#define RTOT  (BATCH*T)   // 98304

// ---------------- scratch (static device memory; no allocations) ----------------
__device__ uint4 g_xh4[(size_t)RTOT * C / 8];       // LN(x) fp16
__device__ uint4 g_ch4[(size_t)RTOT * C / 8];       // LN(cx) fp16
__device__ uint4 g_wh4[(size_t)3 * C * C / 8];      // W fp16
__device__ uint4 g_qh4[(size_t)RTOT * C / 8];       // q fp16
__device__ uint4 g_kh4[(size_t)RTOT * C / 8];       // k fp16
__device__ uint4 g_vh4[(size_t)RTOT * C / 8];       // v fp16

// ---------------- helpers ----------------
__device__ __forceinline__ uint32_t smem_u32(const void* p) {
    uint32_t a;
    asm("{ .reg .u64 t; cvta.to.shared.u64 t, %1; cvt.u32.u64 %0, t; }" : "=r"(a) : "l"(p));
    return a;
}
__device__ __forceinline__ void cp16(uint32_t dst, const void* src) {
    asm volatile("cp.async.cg.shared.global [%0], [%1], 16;" :: "r"(dst), "l"(src));
}
#define CP_COMMIT() asm volatile("cp.async.commit_group;" ::: "memory")
#define CP_WAIT2()  asm volatile("cp.async.wait_group 2;" ::: "memory")
#define CP_WAIT1()  asm volatile("cp.async.wait_group 1;" ::: "memory")
#define CP_WAIT0()  asm volatile("cp.async.wait_group 0;" ::: "memory")

__device__ __forceinline__ void ldsm_x4(uint32_t* r, uint32_t addr) {
    asm volatile("ldmatrix.sync.aligned.m8n8.x4.shared.b16 {%0,%1,%2,%3}, [%4];"
                 : "=r"(r[0]), "=r"(r[1]), "=r"(r[2]), "=r"(r[3]) : "r"(addr));
}
__device__ __forceinline__ void ldsm_x4_t(uint32_t* r, uint32_t addr) {
    asm volatile("ldmatrix.sync.aligned.m8n8.x4.trans.shared.b16 {%0,%1,%2,%3}, [%4];"
                 : "=r"(r[0]), "=r"(r[1]), "=r"(r[2]), "=r"(r[3]) : "r"(addr));
}
__device__ __forceinline__ void mma16816(float* c, const uint32_t* a,
                                         uint32_t b0, uint32_t b1) {
    asm volatile("mma.sync.aligned.m16n8k16.row.col.f32.f16.f16.f32 "
                 "{%0,%1,%2,%3}, {%4,%5,%6,%7}, {%8,%9}, {%0,%1,%2,%3};"
                 : "+f"(c[0]), "+f"(c[1]), "+f"(c[2]), "+f"(c[3])
                 : "r"(a[0]), "r"(a[1]), "r"(a[2]), "r"(a[3]), "r"(b0), "r"(b1));
}
__device__ __forceinline__ uint32_t pack_hi(float f0, float f1) {
    __half2 hp(__float2half_rn(f0), __float2half_rn(f1));
    return *reinterpret_cast<uint32_t*>(&hp);
}

// ---------------- kernel 1: LN stats + apply + fp16 pack ----------------
__global__ void ln_pack_kernel(const float* __restrict__ x, const float* __restrict__ cx,
                               const float* __restrict__ gamma, const float* __restrict__ beta) {
    int warp = threadIdx.x >> 5, lane = threadIdx.x & 31;
    int row = blockIdx.x * 8 + warp;
    const float* src = (row < RTOT) ? x : cx;
    int r  = (row < RTOT) ? row : row - RTOT;
    int bidx = r >> 8;
    int t    = r & 255;
    int bb = bidx / NJ, n = bidx % NJ;
    const float4* p = (const float4*)(src + ((size_t)(bb * T + t) * NJ + n) * C);
    float4 v[4];
    float s = 0.f, sq = 0.f;
#pragma unroll
    for (int i = 0; i < 4; i++) {
        v[i] = p[lane + 32 * i];
        s  += v[i].x + v[i].y + v[i].z + v[i].w;
        sq += v[i].x * v[i].x + v[i].y * v[i].y + v[i].z * v[i].z + v[i].w * v[i].w;
    }
#pragma unroll
    for (int o = 16; o; o >>= 1) {
        s  += __shfl_xor_sync(0xffffffffu, s, o);
        sq += __shfl_xor_sync(0xffffffffu, sq, o);
    }
    float mu = s * (1.0f / C);
    float rs = rsqrtf(sq * (1.0f / C) - mu * mu + 1e-5f);

    __half* dh = (row < RTOT) ? (__half*)g_xh4 : (__half*)g_ch4;
    size_t rb = (size_t)r * C;
#pragma unroll
    for (int i = 0; i < 4; i++) {
        int e = (lane + 32 * i) * 4;
        float4 g  = *(const float4*)(gamma + e);
        float4 be = *(const float4*)(beta + e);
        float f0 = (v[i].x - mu) * rs * g.x + be.x;
        float f1 = (v[i].y - mu) * rs * g.y + be.y;
        float f2 = (v[i].z - mu) * rs * g.z + be.z;
        float f3 = (v[i].w - mu) * rs * g.w + be.w;
        *(uint2*)(dh + rb + e) = make_uint2(pack_hi(f0, f1), pack_hi(f2, f3));
    }
}

// ---------------- kernel 2: pack weights fp16 ----------------
__global__ void pack_w_kernel(const float* __restrict__ Wq, const float* __restrict__ Wk,
                              const float* __restrict__ Wv) {
    size_t e = ((size_t)blockIdx.x * 256 + threadIdx.x) * 4;
    int z = (int)(e / ((size_t)C * C));
    size_t rem = e % ((size_t)C * C);
    const float* W = (z == 0) ? Wq : (z == 1) ? Wk : Wv;
    float4 w = *(const float4*)(W + rem);
    *(uint2*)((__half*)g_wh4 + e) = make_uint2(pack_hi(w.x, w.y), pack_hi(w.z, w.w));
}

// ---------------- kernel 3: QKV GEMM, fp16, BM=128/BN=128/BK=32, occ-2 ----
// stage = 16KB: Ah[8K] Bh[8K]; 4 stages = 64KB; 2 CTAs/SM.
// rows 64B (4 x 16B chunks), swizzle chunk ^ ((row>>1)&3).
#define QSTG 16384

__device__ __forceinline__ void qfill(uint32_t s, int k0,
    const __half* Ah_g, const __half* Bh_g, int r0, int o0, int tid) {
#pragma unroll
    for (int j = 0; j < 2; ++j) {   // A: 128 rows x 4 chunks
        int idx = j * 256 + tid;
        int row = idx >> 2, c = idx & 3;
        uint32_t doff = (uint32_t)(row * 64 + ((c ^ ((row >> 1) & 3)) << 4));
        cp16(s + doff, Ah_g + (size_t)(r0 + row) * C + k0 + c * 8);
    }
#pragma unroll
    for (int j = 0; j < 2; ++j) {   // B: 128 rows x 4 chunks
        int idx = j * 256 + tid;
        int row = idx >> 2, c = idx & 3;
        uint32_t doff = (uint32_t)(row * 64 + ((c ^ ((row >> 1) & 3)) << 4));
        cp16(s + 8192 + doff, Bh_g + (size_t)(o0 + row) * C + k0 + c * 8);
    }
}

__global__ __launch_bounds__(256, 2) void qkv_gemm_mma() {
    extern __shared__ char sm[];
    uint32_t sb = smem_u32(sm);
    int tid = threadIdx.x;
    int wid = tid >> 5, lane = tid & 31;
    int wm = wid & 3, wn = wid >> 2;          // 4(M) x 2(N) warps, warp tile 32x64

    int z = blockIdx.z;
    const __half* Ah_g = (z == 0) ? (const __half*)g_xh4 : (const __half*)g_ch4;
    const __half* Bh_g = (const __half*)g_wh4 + (size_t)z * C * C;
    __half* dst = (z == 0) ? (__half*)g_qh4 : (z == 1) ? (__half*)g_kh4 : (__half*)g_vh4;

    int r0 = blockIdx.y * 128;
    int o0 = blockIdx.x * 128;

    float acc[2][8][4];
#pragma unroll
    for (int i = 0; i < 2; i++)
#pragma unroll
        for (int j = 0; j < 8; j++)
#pragma unroll
            for (int q = 0; q < 4; q++) acc[i][j][q] = 0.f;

    int a_row   = wm * 32 + (lane & 15);
    int a_khalf = lane >> 4;
    int b_nrow  = wn * 64 + (lane & 7) + ((lane >> 4) << 3);
    int b_khalf = (lane >> 3) & 1;

    qfill(sb,            0,  Ah_g, Bh_g, r0, o0, tid); CP_COMMIT();
    qfill(sb + QSTG,     32, Ah_g, Bh_g, r0, o0, tid); CP_COMMIT();
    qfill(sb + 2 * QSTG, 64, Ah_g, Bh_g, r0, o0, tid); CP_COMMIT();

    for (int c = 0; c < 16; ++c) {       // 16 chunks of BK=32
        CP_WAIT2();
        __syncthreads();
        if (c + 3 < 16) {
            qfill(sb + ((c + 3) & 3) * QSTG, (c + 3) * 32, Ah_g, Bh_g, r0, o0, tid);
        }
        CP_COMMIT();

        uint32_t base = sb + (c & 3) * QSTG;
#pragma unroll
        for (int ks = 0; ks < 2; ++ks) {
            uint32_t ah[2][4];
#pragma unroll
            for (int mt = 0; mt < 2; ++mt) {
                int row = a_row + mt * 16;
                int ch = ks * 2 + a_khalf;
                uint32_t off = (uint32_t)(row * 64 + ((ch ^ ((row >> 1) & 3)) << 4));
                ldsm_x4(ah[mt], base + off);
            }
            uint32_t bh[4][4];
#pragma unroll
            for (int ng = 0; ng < 4; ++ng) {
                int nr = b_nrow + ng * 16;
                int ch = ks * 2 + b_khalf;
                uint32_t off = (uint32_t)(nr * 64 + ((ch ^ ((nr >> 1) & 3)) << 4));
                ldsm_x4(bh[ng], base + 8192 + off);
            }
#pragma unroll
            for (int mt = 0; mt < 2; ++mt)
#pragma unroll
                for (int ng = 0; ng < 4; ++ng)
#pragma unroll
                    for (int hf = 0; hf < 2; ++hf)
                        mma16816(acc[mt][ng * 2 + hf], ah[mt], bh[ng][2 * hf], bh[ng][2 * hf + 1]);
        }
        __syncthreads();
    }

    // ---- epilogue: fp16 store ----
    int qr = lane >> 2, qc = (lane & 3) * 2;
#pragma unroll
    for (int mt = 0; mt < 2; ++mt) {
        int row = r0 + wm * 32 + mt * 16 + qr;
#pragma unroll
        for (int nt = 0; nt < 8; ++nt) {
            int col = o0 + wn * 64 + nt * 8 + qc;
            float* cc = acc[mt][nt];
            *(uint32_t*)(dst + (size_t)row * C + col)       = pack_hi(cc[0], cc[1]);
            *(uint32_t*)(dst + (size_t)(row + 8) * C + col) = pack_hi(cc[2], cc[3]);
        }
    }
}

// ---------------- kernel 4: attention, 128 queries/CTA, 3-stage streamed KV, occ-2 ----
// block = (bi, h, th); warp w owns queries [th*128 + 16w, +16).
// smem: 3 KV stages (KH 8K + VH 8K each) at 0..48K, Q[16K] at 48K = 64KB total.
#define ASTG 16384
#define AQ   49152
#define ATT_SMEM 65536

__device__ __forceinline__ void kvfill(uint32_t sb, int stage, int nb,
    const __half* kh_g, const __half* vh_g, size_t rbase, int h, int tid) {
    uint32_t s = sb + stage * ASTG;
#pragma unroll
    for (int j = 0; j < 2; ++j) {
        int i = j * 256 + tid;          // 0..511
        int r = i >> 3, c = i & 7;      // local key row 0..63
        uint32_t off = (uint32_t)(r * 128 + ((c ^ (r & 7)) << 4));
        size_t ga = (rbase + nb * 64 + r) * C + h * HD + c * 8;
        cp16(s + off,        kh_g + ga);
        cp16(s + 8192 + off, vh_g + ga);
    }
}

__global__ __launch_bounds__(256, 2) void attn_mma(const float* __restrict__ x,
                                                   float* __restrict__ out) {
    extern __shared__ char sm[];
    uint32_t sb = smem_u32(sm);
    int tid = threadIdx.x;
    int wid = tid >> 5, lane = tid & 31;

    int th = blockIdx.x & 1;
    int bh = blockIdx.x >> 1;
    int bi = bh / H;
    int h  = bh % H;
    size_t rbase = (size_t)bi * T;
    int q0 = th * 128;

    const __half* qh_g = (const __half*)g_qh4;
    const __half* kh_g = (const __half*)g_kh4;
    const __half* vh_g = (const __half*)g_vh4;

    // Q fill: 128 rows x 8 chunks
#pragma unroll
    for (int j = 0; j < 4; ++j) {
        int i = j * 256 + tid;
        int r = i >> 3, c = i & 7;
        uint32_t off = (uint32_t)(AQ + r * 128 + ((c ^ (r & 7)) << 4));
        cp16(sb + off, qh_g + (rbase + q0 + r) * C + h * HD + c * 8);
    }
    kvfill(sb, 0, 0, kh_g, vh_g, rbase, h, tid);
    CP_COMMIT();                         // G0 = Q + KV0
    kvfill(sb, 1, 1, kh_g, vh_g, rbase, h, tid);
    CP_COMMIT();                         // G1 = KV1

    float yacc[8][4];
#pragma unroll
    for (int j = 0; j < 8; j++)
#pragma unroll
        for (int q = 0; q < 4; q++) yacc[j][q] = 0.f;
    float rs[2] = {0.f, 0.f};

    int a_row = wid * 16 + (lane & 15);
    int a_kh  = lane >> 4;
    int b_kr  = (lane & 7) + ((lane >> 4) << 3);
    int b_kh2 = (lane >> 3) & 1;
    int v_kr  = (lane & 7) + (((lane >> 3) & 1) << 3);
    int v_ch  = lane >> 4;

    for (int nb = 0; nb < 4; ++nb) {
        if (nb < 2) {
            kvfill(sb, (nb + 2) % 3, nb + 2, kh_g, vh_g, rbase, h, tid);
            CP_COMMIT();
            CP_WAIT2();                  // ensures group nb complete
        } else if (nb == 2) {
            CP_WAIT1();
        } else {
            CP_WAIT0();
        }
        __syncthreads();

        uint32_t kbase = sb + (nb % 3) * ASTG;

        float sacc[8][4];
#pragma unroll
        for (int j = 0; j < 8; j++)
#pragma unroll
            for (int q = 0; q < 4; q++) sacc[j][q] = 0.f;

        // ---- S = Q K^T (4 k16 steps over hd) ----
#pragma unroll
        for (int kt = 0; kt < 4; ++kt) {
            uint32_t ah[4];
            {
                int ch = kt * 2 + a_kh;
                uint32_t off = (uint32_t)(AQ + a_row * 128 + ((ch ^ (a_row & 7)) << 4));
                ldsm_x4(ah, sb + off);
            }
            uint32_t kbh[4][4];
#pragma unroll
            for (int ng = 0; ng < 4; ++ng) {
                int kr = ng * 16 + b_kr;
                int ch = kt * 2 + b_kh2;
                uint32_t off = (uint32_t)(kr * 128 + ((ch ^ (kr & 7)) << 4));
                ldsm_x4(kbh[ng], kbase + off);
            }
#pragma unroll
            for (int ng = 0; ng < 4; ++ng)
#pragma unroll
                for (int hf = 0; hf < 2; ++hf)
                    mma16816(sacc[ng * 2 + hf], ah, kbh[ng][2 * hf], kbh[ng][2 * hf + 1]);
        }

        // ---- E = exp(S/8); row sums ----
#pragma unroll
        for (int nt = 0; nt < 8; ++nt) {
            float* cc = sacc[nt];
            cc[0] = __expf(cc[0] * 0.125f);
            cc[1] = __expf(cc[1] * 0.125f);
            cc[2] = __expf(cc[2] * 0.125f);
            cc[3] = __expf(cc[3] * 0.125f);
            rs[0] += cc[0] + cc[1];
            rs[1] += cc[2] + cc[3];
        }

        // ---- Y += P V ----
#pragma unroll
        for (int j = 0; j < 4; ++j) {
            uint32_t pah[4];
            pah[0] = pack_hi(sacc[2 * j][0],     sacc[2 * j][1]);
            pah[1] = pack_hi(sacc[2 * j][2],     sacc[2 * j][3]);
            pah[2] = pack_hi(sacc[2 * j + 1][0], sacc[2 * j + 1][1]);
            pah[3] = pack_hi(sacc[2 * j + 1][2], sacc[2 * j + 1][3]);
            uint32_t vbh[4][4];
#pragma unroll
            for (int hdt = 0; hdt < 4; ++hdt) {
                int vr = j * 16 + v_kr;
                int ch = hdt * 2 + v_ch;
                uint32_t off = (uint32_t)(8192 + vr * 128 + ((ch ^ (vr & 7)) << 4));
                ldsm_x4_t(vbh[hdt], kbase + off);
            }
#pragma unroll
            for (int hdt = 0; hdt < 4; ++hdt)
#pragma unroll
                for (int hf = 0; hf < 2; ++hf)
                    mma16816(yacc[hdt * 2 + hf], pah, vbh[hdt][2 * hf], vbh[hdt][2 * hf + 1]);
        }
        __syncthreads();
    }

    // ---- row-sum reduce within quads, normalize, residual add, store ----
#pragma unroll
    for (int i = 0; i < 2; ++i) {
        rs[i] += __shfl_xor_sync(0xffffffffu, rs[i], 1);
        rs[i] += __shfl_xor_sync(0xffffffffu, rs[i], 2);
    }

    int qr = lane >> 2, qc = (lane & 3) * 2;
    int bb = bi / NJ, n = bi % NJ;
    float inv0 = 1.0f / rs[0];
    float inv1 = 1.0f / rs[1];
    int t0 = q0 + wid * 16 + qr;
#pragma unroll
    for (int nt = 0; nt < 8; ++nt) {
        int hd = nt * 8 + qc;
        float* cc = yacc[nt];
        size_t a0 = ((size_t)(bb * T + t0) * NJ + n) * C + h * HD + hd;
        size_t a1 = ((size_t)(bb * T + t0 + 8) * NJ + n) * C + h * HD + hd;
        float2 x0 = *(const float2*)(x + a0);
        float2 x1 = *(const float2*)(x + a1);
        *(float2*)(out + a0) = make_float2(x0.x + cc[0] * inv0, x0.y + cc[1] * inv0);
        *(float2*)(out + a1) = make_float2(x1.x + cc[2] * inv1, x1.y + cc[3] * inv1);
    }
}

// ---------------- launch ----------------
extern "C" void kernel_launch(void* const* d_in, const int* in_sizes, int n_in,
                              void* d_out, int out_size) {
    const float* x     = (const float*)d_in[0];
    const float* cx    = (const float*)d_in[1];
    const float* gamma = (const float*)d_in[2];
    const float* beta  = (const float*)d_in[3];
    const float* Wq    = (const float*)d_in[4];
    const float* Wk    = (const float*)d_in[5];
    const float* Wv    = (const float*)d_in[6];
    float* out = (float*)d_out;

    cudaFuncSetAttribute(qkv_gemm_mma, cudaFuncAttributeMaxDynamicSharedMemorySize, 4 * QSTG);
    cudaFuncSetAttribute(attn_mma, cudaFuncAttributeMaxDynamicSharedMemorySize, ATT_SMEM);

    ln_pack_kernel<<<2 * RTOT / 8, 256>>>(x, cx, gamma, beta);
    pack_w_kernel<<<3 * C * C / 1024, 256>>>(Wq, Wk, Wv);

    dim3 gg(C / 128, RTOT / 128, 3);
    qkv_gemm_mma<<<gg, 256, 4 * QSTG>>>();

    attn_mma<<<BATCH * H * 2, 256, ATT_SMEM>>>(x, out);
}

// round 15
// speedup vs baseline: 8.8758x; 1.0509x over previous
#include <cuda_runtime.h>
#include <cuda_fp16.h>
#include <cstdint>

#define Bb    16
#define T     256
#define NJ    24
#define C     512
#define H     8
#define HD    64
#define BATCH (Bb*NJ)     // 384
#define RTOT  (BATCH*T)   // 98304

// q pre-scale: exp(S*0.125) == exp2(S*0.125*log2(e))
#define QSCALE 0.180336880f

// ---------------- scratch (static device memory; no allocations) ----------------
__device__ uint4 g_xh4[(size_t)RTOT * C / 8];       // LN(x) fp16
__device__ uint4 g_ch4[(size_t)RTOT * C / 8];       // LN(cx) fp16
__device__ uint4 g_wh4[(size_t)3 * C * C / 8];      // W fp16
__device__ uint4 g_qh4[(size_t)RTOT * C / 8];       // q fp16 (pre-scaled)
__device__ uint4 g_kh4[(size_t)RTOT * C / 8];       // k fp16
__device__ uint4 g_vh4[(size_t)RTOT * C / 8];       // v fp16

// ---------------- helpers ----------------
__device__ __forceinline__ uint32_t smem_u32(const void* p) {
    uint32_t a;
    asm("{ .reg .u64 t; cvta.to.shared.u64 t, %1; cvt.u32.u64 %0, t; }" : "=r"(a) : "l"(p));
    return a;
}
__device__ __forceinline__ void cp16(uint32_t dst, const void* src) {
    asm volatile("cp.async.cg.shared.global [%0], [%1], 16;" :: "r"(dst), "l"(src));
}
#define CP_COMMIT() asm volatile("cp.async.commit_group;" ::: "memory")
#define CP_WAIT1()  asm volatile("cp.async.wait_group 1;" ::: "memory")
#define CP_WAIT0()  asm volatile("cp.async.wait_group 0;" ::: "memory")

__device__ __forceinline__ void ldsm_x4(uint32_t* r, uint32_t addr) {
    asm volatile("ldmatrix.sync.aligned.m8n8.x4.shared.b16 {%0,%1,%2,%3}, [%4];"
                 : "=r"(r[0]), "=r"(r[1]), "=r"(r[2]), "=r"(r[3]) : "r"(addr));
}
__device__ __forceinline__ void ldsm_x4_t(uint32_t* r, uint32_t addr) {
    asm volatile("ldmatrix.sync.aligned.m8n8.x4.trans.shared.b16 {%0,%1,%2,%3}, [%4];"
                 : "=r"(r[0]), "=r"(r[1]), "=r"(r[2]), "=r"(r[3]) : "r"(addr));
}
__device__ __forceinline__ void mma16816(float* c, const uint32_t* a,
                                         uint32_t b0, uint32_t b1) {
    asm volatile("mma.sync.aligned.m16n8k16.row.col.f32.f16.f16.f32 "
                 "{%0,%1,%2,%3}, {%4,%5,%6,%7}, {%8,%9}, {%0,%1,%2,%3};"
                 : "+f"(c[0]), "+f"(c[1]), "+f"(c[2]), "+f"(c[3])
                 : "r"(a[0]), "r"(a[1]), "r"(a[2]), "r"(a[3]), "r"(b0), "r"(b1));
}
__device__ __forceinline__ uint32_t pack_hi(float f0, float f1) {
    __half2 hp(__float2half_rn(f0), __float2half_rn(f1));
    return *reinterpret_cast<uint32_t*>(&hp);
}

// ---------------- kernel 1: LN stats + apply + fp16 pack ----------------
__global__ void ln_pack_kernel(const float* __restrict__ x, const float* __restrict__ cx,
                               const float* __restrict__ gamma, const float* __restrict__ beta) {
    int warp = threadIdx.x >> 5, lane = threadIdx.x & 31;
    int row = blockIdx.x * 8 + warp;
    const float* src = (row < RTOT) ? x : cx;
    int r  = (row < RTOT) ? row : row - RTOT;
    int bidx = r >> 8;
    int t    = r & 255;
    int bb = bidx / NJ, n = bidx % NJ;
    const float4* p = (const float4*)(src + ((size_t)(bb * T + t) * NJ + n) * C);
    float4 v[4];
    float s = 0.f, sq = 0.f;
#pragma unroll
    for (int i = 0; i < 4; i++) {
        v[i] = p[lane + 32 * i];
        s  += v[i].x + v[i].y + v[i].z + v[i].w;
        sq += v[i].x * v[i].x + v[i].y * v[i].y + v[i].z * v[i].z + v[i].w * v[i].w;
    }
#pragma unroll
    for (int o = 16; o; o >>= 1) {
        s  += __shfl_xor_sync(0xffffffffu, s, o);
        sq += __shfl_xor_sync(0xffffffffu, sq, o);
    }
    float mu = s * (1.0f / C);
    float rs = rsqrtf(sq * (1.0f / C) - mu * mu + 1e-5f);

    __half* dh = (row < RTOT) ? (__half*)g_xh4 : (__half*)g_ch4;
    size_t rb = (size_t)r * C;
#pragma unroll
    for (int i = 0; i < 4; i++) {
        int e = (lane + 32 * i) * 4;
        float4 g  = *(const float4*)(gamma + e);
        float4 be = *(const float4*)(beta + e);
        float f0 = (v[i].x - mu) * rs * g.x + be.x;
        float f1 = (v[i].y - mu) * rs * g.y + be.y;
        float f2 = (v[i].z - mu) * rs * g.z + be.z;
        float f3 = (v[i].w - mu) * rs * g.w + be.w;
        *(uint2*)(dh + rb + e) = make_uint2(pack_hi(f0, f1), pack_hi(f2, f3));
    }
}

// ---------------- kernel 2: pack weights fp16 ----------------
__global__ void pack_w_kernel(const float* __restrict__ Wq, const float* __restrict__ Wk,
                              const float* __restrict__ Wv) {
    size_t e = ((size_t)blockIdx.x * 256 + threadIdx.x) * 4;
    int z = (int)(e / ((size_t)C * C));
    size_t rem = e % ((size_t)C * C);
    const float* W = (z == 0) ? Wq : (z == 1) ? Wk : Wv;
    float4 w = *(const float4*)(W + rem);
    *(uint2*)((__half*)g_wh4 + e) = make_uint2(pack_hi(w.x, w.y), pack_hi(w.z, w.w));
}

// ---------------- kernel 3: QKV GEMM, fp16, BM=128/BN=128/BK=64, 3-stage, occ-2 ----
// stage = 32KB: Ah[16K] Bh[16K]; 3 stages = 96KB; 2 CTAs/SM.
// rows 128B (8 x 16B chunks), swizzle chunk ^ (row&7).
#define QSTG 32768

__device__ __forceinline__ void qfill(uint32_t s, int k0,
    const __half* Ah_g, const __half* Bh_g, int r0, int o0, int tid) {
#pragma unroll
    for (int j = 0; j < 4; ++j) {   // A: 128 rows x 8 chunks = 1024
        int idx = j * 256 + tid;
        int row = idx >> 3, c = idx & 7;
        uint32_t doff = (uint32_t)(row * 128 + ((c ^ (row & 7)) << 4));
        cp16(s + doff, Ah_g + (size_t)(r0 + row) * C + k0 + c * 8);
    }
#pragma unroll
    for (int j = 0; j < 4; ++j) {   // B: 128 rows x 8 chunks
        int idx = j * 256 + tid;
        int row = idx >> 3, c = idx & 7;
        uint32_t doff = (uint32_t)(row * 128 + ((c ^ (row & 7)) << 4));
        cp16(s + 16384 + doff, Bh_g + (size_t)(o0 + row) * C + k0 + c * 8);
    }
}

__global__ __launch_bounds__(256, 2) void qkv_gemm_mma() {
    extern __shared__ char sm[];
    uint32_t sb = smem_u32(sm);
    int tid = threadIdx.x;
    int wid = tid >> 5, lane = tid & 31;
    int wm = wid & 3, wn = wid >> 2;          // 4(M) x 2(N) warps, warp tile 32x64

    int z = blockIdx.z;
    const __half* Ah_g = (z == 0) ? (const __half*)g_xh4 : (const __half*)g_ch4;
    const __half* Bh_g = (const __half*)g_wh4 + (size_t)z * C * C;
    __half* dst = (z == 0) ? (__half*)g_qh4 : (z == 1) ? (__half*)g_kh4 : (__half*)g_vh4;

    int r0 = blockIdx.y * 128;
    int o0 = blockIdx.x * 128;

    float acc[2][8][4];
#pragma unroll
    for (int i = 0; i < 2; i++)
#pragma unroll
        for (int j = 0; j < 8; j++)
#pragma unroll
            for (int q = 0; q < 4; q++) acc[i][j][q] = 0.f;

    int a_row   = wm * 32 + (lane & 15);
    int a_khalf = lane >> 4;
    int b_nrow  = wn * 64 + (lane & 7) + ((lane >> 4) << 3);
    int b_khalf = (lane >> 3) & 1;

    qfill(sb,        0,  Ah_g, Bh_g, r0, o0, tid); CP_COMMIT();
    qfill(sb + QSTG, 64, Ah_g, Bh_g, r0, o0, tid); CP_COMMIT();

    for (int c = 0; c < 8; ++c) {        // 8 chunks of BK=64
        if (c < 7) CP_WAIT1(); else CP_WAIT0();
        __syncthreads();
        if (c + 2 < 8) {
            qfill(sb + ((c + 2) % 3) * QSTG, (c + 2) * 64, Ah_g, Bh_g, r0, o0, tid);
            CP_COMMIT();
        }

        uint32_t base = sb + (c % 3) * QSTG;
#pragma unroll
        for (int ks = 0; ks < 4; ++ks) {  // 4 x k16 inside BK=64
            uint32_t ah[2][4];
#pragma unroll
            for (int mt = 0; mt < 2; ++mt) {
                int row = a_row + mt * 16;
                int ch = ks * 2 + a_khalf;
                uint32_t off = (uint32_t)(row * 128 + ((ch ^ (row & 7)) << 4));
                ldsm_x4(ah[mt], base + off);
            }
            uint32_t bh[4][4];
#pragma unroll
            for (int ng = 0; ng < 4; ++ng) {
                int nr = b_nrow + ng * 16;
                int ch = ks * 2 + b_khalf;
                uint32_t off = (uint32_t)(nr * 128 + ((ch ^ (nr & 7)) << 4));
                ldsm_x4(bh[ng], base + 16384 + off);
            }
#pragma unroll
            for (int mt = 0; mt < 2; ++mt)
#pragma unroll
                for (int ng = 0; ng < 4; ++ng)
#pragma unroll
                    for (int hf = 0; hf < 2; ++hf)
                        mma16816(acc[mt][ng * 2 + hf], ah[mt], bh[ng][2 * hf], bh[ng][2 * hf + 1]);
        }
        __syncthreads();
    }

    // ---- epilogue: fp16 store (q gets exp2 pre-scale) ----
    float scale = (z == 0) ? QSCALE : 1.0f;
    int qr = lane >> 2, qc = (lane & 3) * 2;
#pragma unroll
    for (int mt = 0; mt < 2; ++mt) {
        int row = r0 + wm * 32 + mt * 16 + qr;
#pragma unroll
        for (int nt = 0; nt < 8; ++nt) {
            int col = o0 + wn * 64 + nt * 8 + qc;
            float* cc = acc[mt][nt];
            *(uint32_t*)(dst + (size_t)row * C + col)       = pack_hi(cc[0] * scale, cc[1] * scale);
            *(uint32_t*)(dst + (size_t)(row + 8) * C + col) = pack_hi(cc[2] * scale, cc[3] * scale);
        }
    }
}

// ---------------- kernel 4: attention, 128 q/CTA, FULLY-RESIDENT KV, occ-2 ----
// block = (bi, h, th); warp w owns queries [th*128 + 16w, +16).
// smem: Q[16K]@0, K[32K]@16K, V[32K]@48K = 80KB. No mainloop barriers.
#define AQ   0
#define AK   16384
#define AV   49152
#define ATT_SMEM 81920

__global__ __launch_bounds__(256, 2) void attn_mma(const float* __restrict__ x,
                                                   float* __restrict__ out) {
    extern __shared__ char sm[];
    uint32_t sb = smem_u32(sm);
    int tid = threadIdx.x;
    int wid = tid >> 5, lane = tid & 31;

    int th = blockIdx.x & 1;
    int bh = blockIdx.x >> 1;
    int bi = bh / H;
    int h  = bh % H;
    size_t rbase = (size_t)bi * T;
    int q0 = th * 128;

    const __half* qh_g = (const __half*)g_qh4;
    const __half* kh_g = (const __half*)g_kh4;
    const __half* vh_g = (const __half*)g_vh4;

    // Q: 128 rows x 8 chunks
#pragma unroll
    for (int j = 0; j < 4; ++j) {
        int i = j * 256 + tid;
        int r = i >> 3, c = i & 7;
        uint32_t off = (uint32_t)(AQ + r * 128 + ((c ^ (r & 7)) << 4));
        cp16(sb + off, qh_g + (rbase + q0 + r) * C + h * HD + c * 8);
    }
    // K, V: 256 rows x 8 chunks each
#pragma unroll
    for (int j = 0; j < 8; ++j) {
        int i = j * 256 + tid;
        int r = i >> 3, c = i & 7;
        uint32_t off = (uint32_t)(r * 128 + ((c ^ (r & 7)) << 4));
        size_t ga = (rbase + r) * C + h * HD + c * 8;
        cp16(sb + AK + off, kh_g + ga);
        cp16(sb + AV + off, vh_g + ga);
    }
    CP_COMMIT();
    CP_WAIT0();
    __syncthreads();          // the ONLY barrier

    float yacc[8][4];
#pragma unroll
    for (int j = 0; j < 8; j++)
#pragma unroll
        for (int q = 0; q < 4; q++) yacc[j][q] = 0.f;
    float rs[2] = {0.f, 0.f};

    int a_row = wid * 16 + (lane & 15);
    int a_kh  = lane >> 4;
    int b_kr  = (lane & 7) + ((lane >> 4) << 3);
    int b_kh2 = (lane >> 3) & 1;
    int v_kr  = (lane & 7) + (((lane >> 3) & 1) << 3);
    int v_ch  = lane >> 4;

#pragma unroll 1
    for (int nb = 0; nb < 4; ++nb) {
        float sacc[8][4];
#pragma unroll
        for (int j = 0; j < 8; j++)
#pragma unroll
            for (int q = 0; q < 4; q++) sacc[j][q] = 0.f;

        // ---- S' = (q*QSCALE) K^T (4 k16 steps over hd) ----
#pragma unroll
        for (int kt = 0; kt < 4; ++kt) {
            uint32_t ah[4];
            {
                int ch = kt * 2 + a_kh;
                uint32_t off = (uint32_t)(AQ + a_row * 128 + ((ch ^ (a_row & 7)) << 4));
                ldsm_x4(ah, sb + off);
            }
            uint32_t kbh[4][4];
#pragma unroll
            for (int ng = 0; ng < 4; ++ng) {
                int kr = nb * 64 + ng * 16 + b_kr;
                int ch = kt * 2 + b_kh2;
                uint32_t off = (uint32_t)(AK + kr * 128 + ((ch ^ (kr & 7)) << 4));
                ldsm_x4(kbh[ng], sb + off);
            }
#pragma unroll
            for (int ng = 0; ng < 4; ++ng)
#pragma unroll
                for (int hf = 0; hf < 2; ++hf)
                    mma16816(sacc[ng * 2 + hf], ah, kbh[ng][2 * hf], kbh[ng][2 * hf + 1]);
        }

        // ---- E = exp2(S') ; row sums ----
#pragma unroll
        for (int nt = 0; nt < 8; ++nt) {
            float* cc = sacc[nt];
            cc[0] = exp2f(cc[0]);
            cc[1] = exp2f(cc[1]);
            cc[2] = exp2f(cc[2]);
            cc[3] = exp2f(cc[3]);
            rs[0] += cc[0] + cc[1];
            rs[1] += cc[2] + cc[3];
        }

        // ---- Y += P V ----
#pragma unroll
        for (int j = 0; j < 4; ++j) {
            uint32_t pah[4];
            pah[0] = pack_hi(sacc[2 * j][0],     sacc[2 * j][1]);
            pah[1] = pack_hi(sacc[2 * j][2],     sacc[2 * j][3]);
            pah[2] = pack_hi(sacc[2 * j + 1][0], sacc[2 * j + 1][1]);
            pah[3] = pack_hi(sacc[2 * j + 1][2], sacc[2 * j + 1][3]);
            uint32_t vbh[4][4];
#pragma unroll
            for (int hdt = 0; hdt < 4; ++hdt) {
                int vr = nb * 64 + j * 16 + v_kr;
                int ch = hdt * 2 + v_ch;
                uint32_t off = (uint32_t)(AV + vr * 128 + ((ch ^ (vr & 7)) << 4));
                ldsm_x4_t(vbh[hdt], sb + off);
            }
#pragma unroll
            for (int hdt = 0; hdt < 4; ++hdt)
#pragma unroll
                for (int hf = 0; hf < 2; ++hf)
                    mma16816(yacc[hdt * 2 + hf], pah, vbh[hdt][2 * hf], vbh[hdt][2 * hf + 1]);
        }
    }

    // ---- row-sum reduce within quads, normalize, residual add, store ----
#pragma unroll
    for (int i = 0; i < 2; ++i) {
        rs[i] += __shfl_xor_sync(0xffffffffu, rs[i], 1);
        rs[i] += __shfl_xor_sync(0xffffffffu, rs[i], 2);
    }

    int qr = lane >> 2, qc = (lane & 3) * 2;
    int bb = bi / NJ, n = bi % NJ;
    float inv0 = 1.0f / rs[0];
    float inv1 = 1.0f / rs[1];
    int t0 = q0 + wid * 16 + qr;
#pragma unroll
    for (int nt = 0; nt < 8; ++nt) {
        int hd = nt * 8 + qc;
        float* cc = yacc[nt];
        size_t a0 = ((size_t)(bb * T + t0) * NJ + n) * C + h * HD + hd;
        size_t a1 = ((size_t)(bb * T + t0 + 8) * NJ + n) * C + h * HD + hd;
        float2 x0 = *(const float2*)(x + a0);
        float2 x1 = *(const float2*)(x + a1);
        *(float2*)(out + a0) = make_float2(x0.x + cc[0] * inv0, x0.y + cc[1] * inv0);
        *(float2*)(out + a1) = make_float2(x1.x + cc[2] * inv1, x1.y + cc[3] * inv1);
    }
}

// ---------------- launch ----------------
extern "C" void kernel_launch(void* const* d_in, const int* in_sizes, int n_in,
                              void* d_out, int out_size) {
    const float* x     = (const float*)d_in[0];
    const float* cx    = (const float*)d_in[1];
    const float* gamma = (const float*)d_in[2];
    const float* beta  = (const float*)d_in[3];
    const float* Wq    = (const float*)d_in[4];
    const float* Wk    = (const float*)d_in[5];
    const float* Wv    = (const float*)d_in[6];
    float* out = (float*)d_out;

    cudaFuncSetAttribute(qkv_gemm_mma, cudaFuncAttributeMaxDynamicSharedMemorySize, 3 * QSTG);
    cudaFuncSetAttribute(attn_mma, cudaFuncAttributeMaxDynamicSharedMemorySize, ATT_SMEM);

    ln_pack_kernel<<<2 * RTOT / 8, 256>>>(x, cx, gamma, beta);
    pack_w_kernel<<<3 * C * C / 1024, 256>>>(Wq, Wk, Wv);

    dim3 gg(C / 128, RTOT / 128, 3);
    qkv_gemm_mma<<<gg, 256, 3 * QSTG>>>();

    attn_mma<<<BATCH * H * 2, 256, ATT_SMEM>>>(x, out);
}